// round 1
// baseline (speedup 1.0000x reference)
#include <cuda_runtime.h>
#include <math.h>

// ---------------- problem constants ----------------
#define BB     64
#define TT     197
#define DIMM   768
#define HEADS  12
#define HD     64
#define MLP_H  3072
#define R_EFF  16
#define TE     99            // even tokens (src side)
#define TO     98            // odd tokens  (dst side)
#define UNM    (TE - R_EFF)  // 83 unmerged
#define TN     (UNM + TO)    // 181 output tokens
#define BT     (BB * TT)     // 12608
#define BTN    (BB * TN)     // 11584
#define LNEPS  1e-5f

// ---------------- scratch (device globals, no allocs) ----------------
__device__ float g_h   [BT  * DIMM];        // ln1 out
__device__ float g_qkv [BT  * 3 * DIMM];    // qkv
__device__ float g_o   [BT  * DIMM];        // attn out
__device__ float g_x1  [BT  * DIMM];        // x + proj
__device__ float g_met [BT  * HD];          // metric (mean over heads of k)
__device__ int   g_rowmap[BB * TE];         // output row of each even token
__device__ float g_nsz [BB * TN];           // merged sizes
__device__ float g_x2  [BTN * DIMM];        // merged tokens
__device__ float g_h2  [BTN * DIMM];        // ln2 out
__device__ float g_g   [BTN * MLP_H];       // fc1+gelu out

// ---------------- layernorm (one block per token, 256 thr) ----------------
__global__ void ln_kernel(const float* __restrict__ x, const float* __restrict__ gam,
                          const float* __restrict__ bet, float* __restrict__ out) {
    int t = blockIdx.x;
    const float* p = x + (size_t)t * DIMM;
    int tid = threadIdx.x;
    float v[3]; float s = 0.f, ss = 0.f;
#pragma unroll
    for (int r = 0; r < 3; r++) { v[r] = p[tid + r * 256]; s += v[r]; ss += v[r] * v[r]; }
#pragma unroll
    for (int off = 16; off; off >>= 1) {
        s  += __shfl_xor_sync(0xffffffffu, s,  off);
        ss += __shfl_xor_sync(0xffffffffu, ss, off);
    }
    __shared__ float sm_s[8], sm_ss[8];
    if ((tid & 31) == 0) { sm_s[tid >> 5] = s; sm_ss[tid >> 5] = ss; }
    __syncthreads();
    if (tid < 32) {
        s  = (tid < 8) ? sm_s[tid]  : 0.f;
        ss = (tid < 8) ? sm_ss[tid] : 0.f;
#pragma unroll
        for (int off = 4; off; off >>= 1) {
            s  += __shfl_xor_sync(0xffffffffu, s,  off);
            ss += __shfl_xor_sync(0xffffffffu, ss, off);
        }
        if (tid == 0) { sm_s[0] = s; sm_ss[0] = ss; }
    }
    __syncthreads();
    float mean = sm_s[0] * (1.f / (float)DIMM);
    float var  = sm_ss[0] * (1.f / (float)DIMM) - mean * mean;
    float rs = rsqrtf(var + LNEPS);
    float* po = out + (size_t)t * DIMM;
#pragma unroll
    for (int r = 0; r < 3; r++) {
        int d = tid + r * 256;
        po[d] = (v[r] - mean) * rs * gam[d] + bet[d];
    }
}

// ---------------- generic fp32 GEMM: C = A[M,K] * B[N,K]^T (+bias)(+res)(gelu?) ----------
// M,N multiples of 64; K multiple of 16. 256 threads, 64x64 tile, 4x4 per thread.
template <bool GELU>
__global__ void gemm_kernel(const float* __restrict__ A, const float* __restrict__ Bw,
                            const float* __restrict__ bias, const float* __restrict__ res,
                            float* __restrict__ C, int M, int N, int K) {
    __shared__ float As[16][65];
    __shared__ float Bs[16][65];
    int tid = threadIdx.x;
    int tx = tid & 15, ty = tid >> 4;
    int bm = blockIdx.y * 64, bn = blockIdx.x * 64;
    const float* Ab = A  + (size_t)bm * K;
    const float* Bb = Bw + (size_t)bn * K;
    float acc[4][4] = {};
    for (int k0 = 0; k0 < K; k0 += 16) {
#pragma unroll
        for (int r = 0; r < 4; r++) {
            int row = ty + r * 16;
            As[tx][row] = Ab[(size_t)row * K + k0 + tx];
            Bs[tx][row] = Bb[(size_t)row * K + k0 + tx];
        }
        __syncthreads();
#pragma unroll
        for (int kk = 0; kk < 16; kk++) {
            float a[4], b[4];
#pragma unroll
            for (int i = 0; i < 4; i++) a[i] = As[kk][ty * 4 + i];
#pragma unroll
            for (int j = 0; j < 4; j++) b[j] = Bs[kk][tx * 4 + j];
#pragma unroll
            for (int i = 0; i < 4; i++)
#pragma unroll
                for (int j = 0; j < 4; j++) acc[i][j] += a[i] * b[j];
        }
        __syncthreads();
    }
#pragma unroll
    for (int i = 0; i < 4; i++) {
        int m = bm + ty * 4 + i;
#pragma unroll
        for (int j = 0; j < 4; j++) {
            int n = bn + tx * 4 + j;
            float v = acc[i][j];
            if (bias) v += bias[n];
            if (res)  v += res[(size_t)m * N + n];
            if (GELU) v = 0.5f * v * (1.f + erff(v * 0.70710678118654752f));
            C[(size_t)m * N + n] = v;
        }
    }
}

// ---------------- attention: one block per (b,h), 8 warps ----------------
// smem: Ks[197*65], Vs[197*65], qs[8*64], ps[8*197], Ls[197]
#define ATTN_SMEM ((TT * 65 * 2 + 8 * 64 + 8 * TT + TT) * 4)
__global__ void attn_kernel(const float* __restrict__ attn_size) {
    extern __shared__ float sm[];
    float* Ks = sm;
    float* Vs = Ks + TT * 65;
    float* qs = Vs + TT * 65;
    float* ps = qs + 8 * 64;
    float* Ls = ps + 8 * TT;
    int bh = blockIdx.x;
    int b = bh / HEADS, h = bh % HEADS;
    int tid = threadIdx.x, w = tid >> 5, l = tid & 31;

    for (int idx = tid; idx < TT * HD; idx += 256) {
        int j = idx >> 6, d = idx & 63;
        const float* base = g_qkv + (size_t)(b * TT + j) * (3 * DIMM) + h * HD + d;
        Ks[j * 65 + d] = base[DIMM];
        Vs[j * 65 + d] = base[2 * DIMM];
    }
    for (int j = tid; j < TT; j += 256) Ls[j] = logf(attn_size[b * TT + j]);
    __syncthreads();

    const float scale = 0.125f; // 1/sqrt(64)
    for (int i = w; i < TT; i += 8) {
        const float* qp = g_qkv + (size_t)(b * TT + i) * (3 * DIMM) + h * HD;
        qs[w * 64 + l]      = qp[l];
        qs[w * 64 + l + 32] = qp[l + 32];
        __syncwarp();
        float sreg[7];
        float mx = -INFINITY;
        int cnt = 0;
        for (int j = l; j < TT; j += 32, cnt++) {
            float s = 0.f;
#pragma unroll
            for (int d = 0; d < HD; d++) s += qs[w * 64 + d] * Ks[j * 65 + d];
            s = s * scale + Ls[j];
            sreg[cnt] = s;
            mx = fmaxf(mx, s);
        }
#pragma unroll
        for (int off = 16; off; off >>= 1) mx = fmaxf(mx, __shfl_xor_sync(0xffffffffu, mx, off));
        float sum = 0.f;
        cnt = 0;
        for (int j = l; j < TT; j += 32, cnt++) {
            float e = expf(sreg[cnt] - mx);
            sreg[cnt] = e;
            sum += e;
        }
#pragma unroll
        for (int off = 16; off; off >>= 1) sum += __shfl_xor_sync(0xffffffffu, sum, off);
        float inv = 1.f / sum;
        cnt = 0;
        for (int j = l; j < TT; j += 32, cnt++) ps[w * TT + j] = sreg[cnt] * inv;
        __syncwarp();
#pragma unroll
        for (int dd = 0; dd < 2; dd++) {
            int d = l + dd * 32;
            float acc = 0.f;
            for (int j = 0; j < TT; j++) acc += ps[w * TT + j] * Vs[j * 65 + d];
            g_o[(size_t)(b * TT + i) * DIMM + h * HD + d] = acc;
        }
        __syncwarp();
    }
}

// ---------------- metric = mean over heads of k ----------------
__global__ void metric_kernel() {
    int idx = blockIdx.x * blockDim.x + threadIdx.x;
    if (idx >= BT * HD) return;
    int d = idx & 63, bt = idx >> 6;
    float s = 0.f;
#pragma unroll
    for (int h = 0; h < HEADS; h++) s += g_qkv[(size_t)bt * (3 * DIMM) + DIMM + h * HD + d];
    g_met[idx] = s * (1.f / (float)HEADS);
}

// ---------------- matching: one block per batch ----------------
#define MATCH_SMEM (TT * 65 * 4)
__global__ void match_kernel(const float* __restrict__ attn_size, float* __restrict__ rci_out) {
    extern __shared__ float m_s[]; // [197][65] normalized metric
    __shared__ float node_max[TE];
    __shared__ int   node_idx[TE];
    __shared__ int   rank_s[TE];
    __shared__ int   rowmap_s[TE];
    __shared__ float sizes_s[TN];
    int b = blockIdx.x;
    int tid = threadIdx.x, w = tid >> 5, l = tid & 31;

    // normalize metric rows
    for (int t = w; t < TT; t += 8) {
        float v0 = g_met[(size_t)(b * TT + t) * HD + l];
        float v1 = g_met[(size_t)(b * TT + t) * HD + l + 32];
        float ss = v0 * v0 + v1 * v1;
#pragma unroll
        for (int off = 16; off; off >>= 1) ss += __shfl_xor_sync(0xffffffffu, ss, off);
        float nrm = sqrtf(ss);
        m_s[t * 65 + l]      = v0 / nrm;
        m_s[t * 65 + l + 32] = v1 / nrm;
    }
    __syncthreads();

    // per even-row max & argmax (first-max tie-break, matching jnp)
    for (int i = w; i < TE; i += 8) {
        float bm = -INFINITY; int bi = 0;
        if (i != 0) {
            for (int j = l; j < TO; j += 32) {
                float s = 0.f;
#pragma unroll
                for (int d = 0; d < HD; d++) s += m_s[(2 * i) * 65 + d] * m_s[(2 * j + 1) * 65 + d];
                if (s > bm) { bm = s; bi = j; }
            }
        }
#pragma unroll
        for (int off = 16; off; off >>= 1) {
            float om = __shfl_xor_sync(0xffffffffu, bm, off);
            int   oi = __shfl_xor_sync(0xffffffffu, bi, off);
            if (om > bm || (om == bm && oi < bi)) { bm = om; bi = oi; }
        }
        if (l == 0) { node_max[i] = bm; node_idx[i] = bi; }
    }
    __syncthreads();

    // stable descending rank == argsort(-node_max)
    if (tid < TE) {
        float v = node_max[tid];
        int c = 0;
        for (int j = 0; j < TE; j++) {
            float u = node_max[j];
            if (u > v || (u == v && j < tid)) c++;
        }
        rank_s[tid] = c;
    }
    __syncthreads();

    // output row of each even token
    if (tid < TE) {
        int row;
        if (rank_s[tid] >= R_EFF) {
            int c = 0;
            for (int j = 0; j < tid; j++) if (rank_s[j] >= R_EFF) c++;
            row = c;
        } else {
            row = UNM + node_idx[tid];
        }
        rowmap_s[tid] = row;
        g_rowmap[b * TE + tid] = row;
    }
    for (int r = tid; r < TN; r += 256) sizes_s[r] = 0.f;
    __syncthreads();

    // sizes and rci
    for (int t = tid; t < TT; t += 256) {
        int row = (t & 1) ? (UNM + (t >> 1)) : rowmap_s[t >> 1];
        atomicAdd(&sizes_s[row], attn_size[b * TT + t]);
        if (t >= 1) rci_out[(size_t)b * (TT - 1) + (t - 1)] = (float)(row - 1);
    }
    __syncthreads();
    for (int r = tid; r < TN; r += 256) g_nsz[b * TN + r] = sizes_s[r];
}

// ---------------- merge ----------------
__global__ void zero_x2() {
    int i = blockIdx.x * blockDim.x + threadIdx.x;
    if (i < BTN * DIMM) g_x2[i] = 0.f;
}

__global__ void merge_kernel(const float* __restrict__ attn_size) {
    int bt = blockIdx.x;
    int b = bt / TT, t = bt % TT;
    int row = (t & 1) ? (UNM + (t >> 1)) : g_rowmap[b * TE + (t >> 1)];
    float s = attn_size[bt];
    const float* src = g_x1 + (size_t)bt * DIMM;
    float* dst = g_x2 + ((size_t)b * TN + row) * DIMM;
    for (int d = threadIdx.x; d < DIMM; d += 256) atomicAdd(&dst[d], src[d] * s);
}

__global__ void finalize_kernel(float* __restrict__ out_ns) {
    int br = blockIdx.x; // b*TN + r
    float ns = g_nsz[br];
    if (threadIdx.x == 0) out_ns[br] = ns;
    float* p = g_x2 + (size_t)br * DIMM;
    for (int d = threadIdx.x; d < DIMM; d += 256) p[d] = p[d] / ns;
}

// ---------------- launch ----------------
extern "C" void kernel_launch(void* const* d_in, const int* in_sizes, int n_in,
                              void* d_out, int out_size) {
    const float* x         = (const float*)d_in[0];
    const float* attn_size = (const float*)d_in[1];
    const float* ln1_g     = (const float*)d_in[2];
    const float* ln1_b     = (const float*)d_in[3];
    const float* w_qkv     = (const float*)d_in[4];
    const float* w_proj    = (const float*)d_in[5];
    const float* b_proj    = (const float*)d_in[6];
    const float* ln2_g     = (const float*)d_in[7];
    const float* ln2_b     = (const float*)d_in[8];
    const float* w_fc1     = (const float*)d_in[9];
    const float* b_fc1     = (const float*)d_in[10];
    const float* w_fc2     = (const float*)d_in[11];
    const float* b_fc2     = (const float*)d_in[12];

    float* out_x   = (float*)d_out;                         // [64,181,768]
    float* out_ns  = out_x + (size_t)BTN * DIMM;            // [64,181]
    float* out_rci = out_ns + BTN;                          // [64,196]

    cudaFuncSetAttribute(attn_kernel, cudaFuncAttributeMaxDynamicSharedMemorySize, ATTN_SMEM);
    cudaFuncSetAttribute(match_kernel, cudaFuncAttributeMaxDynamicSharedMemorySize, MATCH_SMEM);

    // scratch pointers (device globals referenced directly inside kernels)
    float *g_h_p, *g_o_p, *g_x2_p, *g_h2_p, *g_g_p, *g_qkv_p, *g_x1_p;
    cudaGetSymbolAddress((void**)&g_h_p,  g_h);
    cudaGetSymbolAddress((void**)&g_o_p,  g_o);
    cudaGetSymbolAddress((void**)&g_x2_p, g_x2);
    cudaGetSymbolAddress((void**)&g_h2_p, g_h2);
    cudaGetSymbolAddress((void**)&g_g_p,  g_g);
    cudaGetSymbolAddress((void**)&g_qkv_p, g_qkv);
    cudaGetSymbolAddress((void**)&g_x1_p, g_x1);

    // 1) LN1
    ln_kernel<<<BT, 256>>>(x, ln1_g, ln1_b, g_h_p);
    // 2) qkv = h @ w_qkv^T  : [12608,768] x [2304,768]^T
    gemm_kernel<false><<<dim3(3 * DIMM / 64, BT / 64), 256>>>(g_h_p, w_qkv, nullptr, nullptr,
                                                              g_qkv_p, BT, 3 * DIMM, DIMM);
    // 3) attention
    attn_kernel<<<BB * HEADS, 256, ATTN_SMEM>>>(attn_size);
    // 4) x1 = x + o @ w_proj^T + b_proj
    gemm_kernel<false><<<dim3(DIMM / 64, BT / 64), 256>>>(g_o_p, w_proj, b_proj, x,
                                                          g_x1_p, BT, DIMM, DIMM);
    // 5) metric
    metric_kernel<<<(BT * HD + 255) / 256, 256>>>();
    // 6) matching (+ rci)
    match_kernel<<<BB, 256, MATCH_SMEM>>>(attn_size, out_rci);
    // 7-9) merge, normalize, new_size
    zero_x2<<<(BTN * DIMM + 255) / 256, 256>>>();
    merge_kernel<<<BT, 256>>>(attn_size);
    finalize_kernel<<<BTN, 256>>>(out_ns);
    // 10) LN2
    ln_kernel<<<BTN, 256>>>(g_x2_p, ln2_g, ln2_b, g_h2_p);
    // 11) MLP
    gemm_kernel<true><<<dim3(MLP_H / 64, BTN / 64), 256>>>(g_h2_p, w_fc1, b_fc1, nullptr,
                                                           g_g_p, BTN, MLP_H, DIMM);
    gemm_kernel<false><<<dim3(DIMM / 64, BTN / 64), 256>>>(g_g_p, w_fc2, b_fc2, g_x2_p,
                                                           out_x, BTN, DIMM, MLP_H);
}

// round 2
// speedup vs baseline: 1.7185x; 1.7185x over previous
#include <cuda_runtime.h>
#include <math.h>

// ---------------- problem constants ----------------
#define BB     64
#define TT     197
#define DIMM   768
#define HEADS  12
#define HD     64
#define MLP_H  3072
#define R_EFF  16
#define TE     99            // even tokens (src side)
#define TO     98            // odd tokens  (dst side)
#define UNM    (TE - R_EFF)  // 83 unmerged
#define TN     (UNM + TO)    // 181 output tokens
#define BT     (BB * TT)     // 12608
#define BTN    (BB * TN)     // 11584
#define LNEPS  1e-5f

// ---------------- scratch (device globals, no allocs) ----------------
__device__ float g_h   [BT  * DIMM];        // ln1 out
__device__ float g_qkv [BT  * 3 * DIMM];    // qkv
__device__ float g_o   [BT  * DIMM];        // attn out
__device__ float g_x1  [BT  * DIMM];        // x + proj
__device__ float g_met [BT  * HD];          // metric (mean over heads of k)
__device__ int   g_rowmap[BB * TE];         // output row of each even token
__device__ float g_nsz [BB * TN];           // merged sizes
__device__ float g_x2  [BTN * DIMM];        // merged tokens
__device__ float g_h2  [BTN * DIMM];        // ln2 out
__device__ float g_g   [BTN * MLP_H];       // fc1+gelu out

// ---------------- layernorm (one block per token, 256 thr) ----------------
__global__ void ln_kernel(const float* __restrict__ x, const float* __restrict__ gam,
                          const float* __restrict__ bet, float* __restrict__ out) {
    int t = blockIdx.x;
    const float* p = x + (size_t)t * DIMM;
    int tid = threadIdx.x;
    float v[3]; float s = 0.f, ss = 0.f;
#pragma unroll
    for (int r = 0; r < 3; r++) { v[r] = p[tid + r * 256]; s += v[r]; ss += v[r] * v[r]; }
#pragma unroll
    for (int off = 16; off; off >>= 1) {
        s  += __shfl_xor_sync(0xffffffffu, s,  off);
        ss += __shfl_xor_sync(0xffffffffu, ss, off);
    }
    __shared__ float sm_s[8], sm_ss[8];
    if ((tid & 31) == 0) { sm_s[tid >> 5] = s; sm_ss[tid >> 5] = ss; }
    __syncthreads();
    if (tid < 32) {
        s  = (tid < 8) ? sm_s[tid]  : 0.f;
        ss = (tid < 8) ? sm_ss[tid] : 0.f;
#pragma unroll
        for (int off = 4; off; off >>= 1) {
            s  += __shfl_xor_sync(0xffffffffu, s,  off);
            ss += __shfl_xor_sync(0xffffffffu, ss, off);
        }
        if (tid == 0) { sm_s[0] = s; sm_ss[0] = ss; }
    }
    __syncthreads();
    float mean = sm_s[0] * (1.f / (float)DIMM);
    float var  = sm_ss[0] * (1.f / (float)DIMM) - mean * mean;
    float rs = rsqrtf(var + LNEPS);
    float* po = out + (size_t)t * DIMM;
#pragma unroll
    for (int r = 0; r < 3; r++) {
        int d = tid + r * 256;
        po[d] = (v[r] - mean) * rs * gam[d] + bet[d];
    }
}

// ---------------- fast fp32 GEMM: C = A[M,K] * B[N,K]^T (+bias)(+res)(gelu?) ----------
// 128x128 block tile, 16 k-tile, 8x8 per-thread microtile, double-buffered smem,
// all inner-loop smem reads are LDS.128. N must be a multiple of 128; K of 16.
// M is arbitrary (loads clamped, stores predicated).
template <bool GELU>
__global__ void __launch_bounds__(256, 2) gemm_kernel(
    const float* __restrict__ A, const float* __restrict__ Bw,
    const float* __restrict__ bias, const float* __restrict__ res,
    float* __restrict__ C, int M, int N, int K)
{
    __shared__ float As[2][16][128];
    __shared__ float Bs[2][16][128];
    int tid = threadIdx.x;
    int tx = tid & 15, ty = tid >> 4;
    int bm = blockIdx.y * 128, bn = blockIdx.x * 128;

    int arow = tid >> 2;            // 0..63 (second fragment at +64)
    int akq  = (tid & 3) * 4;       // 0,4,8,12
    const int KT = K >> 4;

    // clamped global row bases (avoid OOB reads on M tail)
    size_t aoff[2], boff[2];
#pragma unroll
    for (int i = 0; i < 2; i++) {
        int gm = bm + arow + i * 64; if (gm > M - 1) gm = M - 1;
        aoff[i] = (size_t)gm * K + akq;
        boff[i] = (size_t)(bn + arow + i * 64) * K + akq;
    }

    float4 la[2], lb[2];
#pragma unroll
    for (int i = 0; i < 2; i++) {
        la[i] = *(const float4*)&A [aoff[i]];
        lb[i] = *(const float4*)&Bw[boff[i]];
    }
#pragma unroll
    for (int i = 0; i < 2; i++) {
        int r = arow + i * 64;
        As[0][akq + 0][r] = la[i].x; As[0][akq + 1][r] = la[i].y;
        As[0][akq + 2][r] = la[i].z; As[0][akq + 3][r] = la[i].w;
        Bs[0][akq + 0][r] = lb[i].x; Bs[0][akq + 1][r] = lb[i].y;
        Bs[0][akq + 2][r] = lb[i].z; Bs[0][akq + 3][r] = lb[i].w;
    }
    __syncthreads();

    float acc[8][8] = {};
    for (int kt = 0; kt < KT; kt++) {
        int s = kt & 1;
        if (kt + 1 < KT) {
            size_t ko = (size_t)((kt + 1) << 4);
#pragma unroll
            for (int i = 0; i < 2; i++) {
                la[i] = *(const float4*)&A [aoff[i] + ko];
                lb[i] = *(const float4*)&Bw[boff[i] + ko];
            }
        }
#pragma unroll
        for (int kk = 0; kk < 16; kk++) {
            float4 a0 = *(const float4*)&As[s][kk][ty * 4];
            float4 a1 = *(const float4*)&As[s][kk][ty * 4 + 64];
            float4 b0 = *(const float4*)&Bs[s][kk][tx * 4];
            float4 b1 = *(const float4*)&Bs[s][kk][tx * 4 + 64];
            float av[8] = {a0.x, a0.y, a0.z, a0.w, a1.x, a1.y, a1.z, a1.w};
            float bv[8] = {b0.x, b0.y, b0.z, b0.w, b1.x, b1.y, b1.z, b1.w};
#pragma unroll
            for (int i = 0; i < 8; i++)
#pragma unroll
                for (int j = 0; j < 8; j++) acc[i][j] += av[i] * bv[j];
        }
        if (kt + 1 < KT) {
            int s2 = s ^ 1;
#pragma unroll
            for (int i = 0; i < 2; i++) {
                int r = arow + i * 64;
                As[s2][akq + 0][r] = la[i].x; As[s2][akq + 1][r] = la[i].y;
                As[s2][akq + 2][r] = la[i].z; As[s2][akq + 3][r] = la[i].w;
                Bs[s2][akq + 0][r] = lb[i].x; Bs[s2][akq + 1][r] = lb[i].y;
                Bs[s2][akq + 2][r] = lb[i].z; Bs[s2][akq + 3][r] = lb[i].w;
            }
            __syncthreads();
        }
    }

    // epilogue
#pragma unroll
    for (int im = 0; im < 2; im++) {
#pragma unroll
        for (int ii = 0; ii < 4; ii++) {
            int m = bm + im * 64 + ty * 4 + ii;
            if (m >= M) continue;
            int ai = im * 4 + ii;
#pragma unroll
            for (int jn = 0; jn < 2; jn++) {
                int n0 = bn + jn * 64 + tx * 4;
                float4 v;
                v.x = acc[ai][jn * 4 + 0]; v.y = acc[ai][jn * 4 + 1];
                v.z = acc[ai][jn * 4 + 2]; v.w = acc[ai][jn * 4 + 3];
                if (bias) {
                    float4 bb = *(const float4*)&bias[n0];
                    v.x += bb.x; v.y += bb.y; v.z += bb.z; v.w += bb.w;
                }
                if (res) {
                    float4 rr = *(const float4*)&res[(size_t)m * N + n0];
                    v.x += rr.x; v.y += rr.y; v.z += rr.z; v.w += rr.w;
                }
                if (GELU) {
                    v.x = 0.5f * v.x * (1.f + erff(v.x * 0.70710678118654752f));
                    v.y = 0.5f * v.y * (1.f + erff(v.y * 0.70710678118654752f));
                    v.z = 0.5f * v.z * (1.f + erff(v.z * 0.70710678118654752f));
                    v.w = 0.5f * v.w * (1.f + erff(v.w * 0.70710678118654752f));
                }
                *(float4*)&C[(size_t)m * N + n0] = v;
            }
        }
    }
}

// ---------------- attention: one block per (b,h), 8 warps ----------------
// K/V rows padded to 68 floats for conflict-free float4 LDS.
#define KVP 68
#define ATTN_SMEM ((TT * KVP * 2 + 8 * 64 + 8 * TT + TT) * 4)
__global__ void attn_kernel(const float* __restrict__ attn_size) {
    extern __shared__ float sm[];
    float* Ks = sm;
    float* Vs = Ks + TT * KVP;
    float* qs = Vs + TT * KVP;
    float* ps = qs + 8 * 64;
    float* Ls = ps + 8 * TT;
    int bh = blockIdx.x;
    int b = bh / HEADS, h = bh % HEADS;
    int tid = threadIdx.x, w = tid >> 5, l = tid & 31;

    for (int idx = tid; idx < TT * HD; idx += 256) {
        int j = idx >> 6, d = idx & 63;
        const float* base = g_qkv + (size_t)(b * TT + j) * (3 * DIMM) + h * HD + d;
        Ks[j * KVP + d] = base[DIMM];
        Vs[j * KVP + d] = base[2 * DIMM];
    }
    for (int j = tid; j < TT; j += 256) Ls[j] = logf(attn_size[b * TT + j]);
    __syncthreads();

    const float scale = 0.125f; // 1/sqrt(64)
    for (int i = w; i < TT; i += 8) {
        const float* qp = g_qkv + (size_t)(b * TT + i) * (3 * DIMM) + h * HD;
        qs[w * 64 + l]      = qp[l];
        qs[w * 64 + l + 32] = qp[l + 32];
        __syncwarp();
        const float4* q4 = (const float4*)&qs[w * 64];
        float sreg[7];
        float mx = -INFINITY;
        int cnt = 0;
        for (int j = l; j < TT; j += 32, cnt++) {
            const float4* k4 = (const float4*)&Ks[j * KVP];
            float s = 0.f;
#pragma unroll
            for (int d4 = 0; d4 < 16; d4++) {
                float4 kv = k4[d4], qv = q4[d4];
                s += qv.x * kv.x + qv.y * kv.y + qv.z * kv.z + qv.w * kv.w;
            }
            s = s * scale + Ls[j];
            sreg[cnt] = s;
            mx = fmaxf(mx, s);
        }
#pragma unroll
        for (int off = 16; off; off >>= 1) mx = fmaxf(mx, __shfl_xor_sync(0xffffffffu, mx, off));
        float sum = 0.f;
        cnt = 0;
        for (int j = l; j < TT; j += 32, cnt++) {
            float e = expf(sreg[cnt] - mx);
            sreg[cnt] = e;
            sum += e;
        }
#pragma unroll
        for (int off = 16; off; off >>= 1) sum += __shfl_xor_sync(0xffffffffu, sum, off);
        float inv = 1.f / sum;
        cnt = 0;
        for (int j = l; j < TT; j += 32, cnt++) ps[w * TT + j] = sreg[cnt] * inv;
        __syncwarp();
#pragma unroll
        for (int dd = 0; dd < 2; dd++) {
            int d = l + dd * 32;
            float acc = 0.f;
            int j = 0;
            for (; j + 4 <= TT; j += 4) {
                acc += ps[w * TT + j + 0] * Vs[(j + 0) * KVP + d];
                acc += ps[w * TT + j + 1] * Vs[(j + 1) * KVP + d];
                acc += ps[w * TT + j + 2] * Vs[(j + 2) * KVP + d];
                acc += ps[w * TT + j + 3] * Vs[(j + 3) * KVP + d];
            }
            for (; j < TT; j++) acc += ps[w * TT + j] * Vs[j * KVP + d];
            g_o[(size_t)(b * TT + i) * DIMM + h * HD + d] = acc;
        }
        __syncwarp();
    }
}

// ---------------- metric = mean over heads of k ----------------
__global__ void metric_kernel() {
    int idx = blockIdx.x * blockDim.x + threadIdx.x;
    if (idx >= BT * HD) return;
    int d = idx & 63, bt = idx >> 6;
    float s = 0.f;
#pragma unroll
    for (int h = 0; h < HEADS; h++) s += g_qkv[(size_t)bt * (3 * DIMM) + DIMM + h * HD + d];
    g_met[idx] = s * (1.f / (float)HEADS);
}

// ---------------- matching: one block per batch ----------------
#define MATCH_SMEM (TT * 65 * 4)
__global__ void match_kernel(const float* __restrict__ attn_size, float* __restrict__ rci_out) {
    extern __shared__ float m_s[]; // [197][65] normalized metric
    __shared__ float node_max[TE];
    __shared__ int   node_idx[TE];
    __shared__ int   rank_s[TE];
    __shared__ int   rowmap_s[TE];
    __shared__ float sizes_s[TN];
    int b = blockIdx.x;
    int tid = threadIdx.x, w = tid >> 5, l = tid & 31;

    // normalize metric rows
    for (int t = w; t < TT; t += 8) {
        float v0 = g_met[(size_t)(b * TT + t) * HD + l];
        float v1 = g_met[(size_t)(b * TT + t) * HD + l + 32];
        float ss = v0 * v0 + v1 * v1;
#pragma unroll
        for (int off = 16; off; off >>= 1) ss += __shfl_xor_sync(0xffffffffu, ss, off);
        float nrm = sqrtf(ss);
        m_s[t * 65 + l]      = v0 / nrm;
        m_s[t * 65 + l + 32] = v1 / nrm;
    }
    __syncthreads();

    // per even-row max & argmax (first-max tie-break, matching jnp)
    for (int i = w; i < TE; i += 8) {
        float bm = -INFINITY; int bi = 0;
        if (i != 0) {
            for (int j = l; j < TO; j += 32) {
                float s = 0.f;
#pragma unroll
                for (int d = 0; d < HD; d++) s += m_s[(2 * i) * 65 + d] * m_s[(2 * j + 1) * 65 + d];
                if (s > bm) { bm = s; bi = j; }
            }
        }
#pragma unroll
        for (int off = 16; off; off >>= 1) {
            float om = __shfl_xor_sync(0xffffffffu, bm, off);
            int   oi = __shfl_xor_sync(0xffffffffu, bi, off);
            if (om > bm || (om == bm && oi < bi)) { bm = om; bi = oi; }
        }
        if (l == 0) { node_max[i] = bm; node_idx[i] = bi; }
    }
    __syncthreads();

    // stable descending rank == argsort(-node_max)
    if (tid < TE) {
        float v = node_max[tid];
        int c = 0;
        for (int j = 0; j < TE; j++) {
            float u = node_max[j];
            if (u > v || (u == v && j < tid)) c++;
        }
        rank_s[tid] = c;
    }
    __syncthreads();

    // output row of each even token
    if (tid < TE) {
        int row;
        if (rank_s[tid] >= R_EFF) {
            int c = 0;
            for (int j = 0; j < tid; j++) if (rank_s[j] >= R_EFF) c++;
            row = c;
        } else {
            row = UNM + node_idx[tid];
        }
        rowmap_s[tid] = row;
        g_rowmap[b * TE + tid] = row;
    }
    for (int r = tid; r < TN; r += 256) sizes_s[r] = 0.f;
    __syncthreads();

    // sizes and rci
    for (int t = tid; t < TT; t += 256) {
        int row = (t & 1) ? (UNM + (t >> 1)) : rowmap_s[t >> 1];
        atomicAdd(&sizes_s[row], attn_size[b * TT + t]);
        if (t >= 1) rci_out[(size_t)b * (TT - 1) + (t - 1)] = (float)(row - 1);
    }
    __syncthreads();
    for (int r = tid; r < TN; r += 256) g_nsz[b * TN + r] = sizes_s[r];
}

// ---------------- merge ----------------
__global__ void zero_x2() {
    int i = blockIdx.x * blockDim.x + threadIdx.x;
    if (i < BTN * DIMM) g_x2[i] = 0.f;
}

__global__ void merge_kernel(const float* __restrict__ attn_size) {
    int bt = blockIdx.x;
    int b = bt / TT, t = bt % TT;
    int row = (t & 1) ? (UNM + (t >> 1)) : g_rowmap[b * TE + (t >> 1)];
    float s = attn_size[bt];
    const float* src = g_x1 + (size_t)bt * DIMM;
    float* dst = g_x2 + ((size_t)b * TN + row) * DIMM;
    for (int d = threadIdx.x; d < DIMM; d += 256) atomicAdd(&dst[d], src[d] * s);
}

__global__ void finalize_kernel(float* __restrict__ out_ns) {
    int br = blockIdx.x; // b*TN + r
    float ns = g_nsz[br];
    if (threadIdx.x == 0) out_ns[br] = ns;
    float* p = g_x2 + (size_t)br * DIMM;
    for (int d = threadIdx.x; d < DIMM; d += 256) p[d] = p[d] / ns;
}

// ---------------- launch ----------------
extern "C" void kernel_launch(void* const* d_in, const int* in_sizes, int n_in,
                              void* d_out, int out_size) {
    const float* x         = (const float*)d_in[0];
    const float* attn_size = (const float*)d_in[1];
    const float* ln1_g     = (const float*)d_in[2];
    const float* ln1_b     = (const float*)d_in[3];
    const float* w_qkv     = (const float*)d_in[4];
    const float* w_proj    = (const float*)d_in[5];
    const float* b_proj    = (const float*)d_in[6];
    const float* ln2_g     = (const float*)d_in[7];
    const float* ln2_b     = (const float*)d_in[8];
    const float* w_fc1     = (const float*)d_in[9];
    const float* b_fc1     = (const float*)d_in[10];
    const float* w_fc2     = (const float*)d_in[11];
    const float* b_fc2     = (const float*)d_in[12];

    float* out_x   = (float*)d_out;                         // [64,181,768]
    float* out_ns  = out_x + (size_t)BTN * DIMM;            // [64,181]
    float* out_rci = out_ns + BTN;                          // [64,196]

    cudaFuncSetAttribute(attn_kernel, cudaFuncAttributeMaxDynamicSharedMemorySize, ATTN_SMEM);
    cudaFuncSetAttribute(match_kernel, cudaFuncAttributeMaxDynamicSharedMemorySize, MATCH_SMEM);

    float *g_h_p, *g_o_p, *g_x2_p, *g_h2_p, *g_g_p, *g_qkv_p, *g_x1_p;
    cudaGetSymbolAddress((void**)&g_h_p,  g_h);
    cudaGetSymbolAddress((void**)&g_o_p,  g_o);
    cudaGetSymbolAddress((void**)&g_x2_p, g_x2);
    cudaGetSymbolAddress((void**)&g_h2_p, g_h2);
    cudaGetSymbolAddress((void**)&g_g_p,  g_g);
    cudaGetSymbolAddress((void**)&g_qkv_p, g_qkv);
    cudaGetSymbolAddress((void**)&g_x1_p, g_x1);

    // 1) LN1
    ln_kernel<<<BT, 256>>>(x, ln1_g, ln1_b, g_h_p);
    // 2) qkv = h @ w_qkv^T : [12608,768] x [2304,768]^T
    gemm_kernel<false><<<dim3(3 * DIMM / 128, (BT + 127) / 128), 256>>>(
        g_h_p, w_qkv, nullptr, nullptr, g_qkv_p, BT, 3 * DIMM, DIMM);
    // 3) attention
    attn_kernel<<<BB * HEADS, 256, ATTN_SMEM>>>(attn_size);
    // 4) x1 = x + o @ w_proj^T + b_proj
    gemm_kernel<false><<<dim3(DIMM / 128, (BT + 127) / 128), 256>>>(
        g_o_p, w_proj, b_proj, x, g_x1_p, BT, DIMM, DIMM);
    // 5) metric
    metric_kernel<<<(BT * HD + 255) / 256, 256>>>();
    // 6) matching (+ rci)
    match_kernel<<<BB, 256, MATCH_SMEM>>>(attn_size, out_rci);
    // 7-9) merge, normalize, new_size
    zero_x2<<<(BTN * DIMM + 255) / 256, 256>>>();
    merge_kernel<<<BT, 256>>>(attn_size);
    finalize_kernel<<<BTN, 256>>>(out_ns);
    // 10) LN2
    ln_kernel<<<BTN, 256>>>(g_x2_p, ln2_g, ln2_b, g_h2_p);
    // 11) MLP
    gemm_kernel<true><<<dim3(MLP_H / 128, (BTN + 127) / 128), 256>>>(
        g_h2_p, w_fc1, b_fc1, nullptr, g_g_p, BTN, MLP_H, DIMM);
    gemm_kernel<false><<<dim3(DIMM / 128, (BTN + 127) / 128), 256>>>(
        g_g_p, w_fc2, b_fc2, g_x2_p, out_x, BTN, DIMM, MLP_H);
}

// round 3
// speedup vs baseline: 2.7856x; 1.6210x over previous
#include <cuda_runtime.h>
#include <math.h>
#include <stdint.h>

// ---------------- problem constants ----------------
#define BB     64
#define TT     197
#define DIMM   768
#define HEADS  12
#define HD     64
#define MLP_H  3072
#define R_EFF  16
#define TE     99
#define TO     98
#define UNM    (TE - R_EFF)  // 83
#define TN     (UNM + TO)    // 181
#define BT     (BB * TT)     // 12608
#define BTN    (BB * TN)     // 11584
#define LNEPS  1e-5f

// ---------------- scratch ----------------
__device__ float g_h   [BT  * DIMM];
__device__ float g_qkv [BT  * 3 * DIMM];
__device__ float g_o   [BT  * DIMM];
__device__ float g_x1  [BT  * DIMM];
__device__ float g_met [BT  * HD];
__device__ float g_wavg[HD * DIMM];
__device__ int   g_rowmap[BB * TE];
__device__ float g_nsz [BB * TN];
__device__ float g_x2  [BTN * DIMM];
__device__ float g_h2  [BTN * DIMM];
__device__ float g_g   [BTN * MLP_H];

// ---------------- layernorm ----------------
__global__ void ln_kernel(const float* __restrict__ x, const float* __restrict__ gam,
                          const float* __restrict__ bet, float* __restrict__ out) {
    int t = blockIdx.x;
    const float* p = x + (size_t)t * DIMM;
    int tid = threadIdx.x;
    float v[3]; float s = 0.f, ss = 0.f;
#pragma unroll
    for (int r = 0; r < 3; r++) { v[r] = p[tid + r * 256]; s += v[r]; ss += v[r] * v[r]; }
#pragma unroll
    for (int off = 16; off; off >>= 1) {
        s  += __shfl_xor_sync(0xffffffffu, s,  off);
        ss += __shfl_xor_sync(0xffffffffu, ss, off);
    }
    __shared__ float sm_s[8], sm_ss[8];
    if ((tid & 31) == 0) { sm_s[tid >> 5] = s; sm_ss[tid >> 5] = ss; }
    __syncthreads();
    if (tid < 32) {
        s  = (tid < 8) ? sm_s[tid]  : 0.f;
        ss = (tid < 8) ? sm_ss[tid] : 0.f;
#pragma unroll
        for (int off = 4; off; off >>= 1) {
            s  += __shfl_xor_sync(0xffffffffu, s,  off);
            ss += __shfl_xor_sync(0xffffffffu, ss, off);
        }
        if (tid == 0) { sm_s[0] = s; sm_ss[0] = ss; }
    }
    __syncthreads();
    float mean = sm_s[0] * (1.f / (float)DIMM);
    float var  = sm_ss[0] * (1.f / (float)DIMM) - mean * mean;
    float rs = rsqrtf(var + LNEPS);
    float* po = out + (size_t)t * DIMM;
#pragma unroll
    for (int r = 0; r < 3; r++) {
        int d = tid + r * 256;
        po[d] = (v[r] - mean) * rs * gam[d] + bet[d];
    }
}

// =====================================================================
// tf32 tensor-core GEMM: C = A[M,K] * B[N,K]^T (+bias)(+res)(gelu)
// BM=128, BN=256, BK=16, 256 threads (8 warps, 2x4 grid, 64x64 warp tile)
// N must be a multiple of 256, K of 16. M arbitrary.
// Smem layout (words):
//   A buf: 16 tiles (mi*2+s) * 140 words; word = tile*140 + kh*68 + lane*2 + rh
//   B buf: [256][20] row-major; word = 2240 + n*20 + k
//   double buffered, buffer stride 7360 words; total 14720 words = 58880 B
// =====================================================================
#define GBUF 7360
#define GSMEM_BYTES (14720 * 4)

__device__ __forceinline__ uint32_t f2tf32(float f) {
    uint32_t o;
    asm("cvt.rna.tf32.f32 %0, %1;" : "=r"(o) : "f"(f));
    return o;
}

template <bool GELU>
__global__ void __launch_bounds__(256) mma_gemm(
    const float* __restrict__ A, const float* __restrict__ Bw,
    const float* __restrict__ bias, const float* __restrict__ res,
    float* __restrict__ C, int M, int N, int K)
{
    extern __shared__ uint32_t sm[];
    const int tid = threadIdx.x;
    const int lane = tid & 31, w = tid >> 5;
    const int wm = w >> 2, wn = w & 3;
    const int gid = lane >> 2, tig = lane & 3;
    const int bm = blockIdx.y * 128, bn = blockIdx.x * 256;
    const int KT = K >> 4;

    // ---- staging address precompute ----
    size_t aOff[2]; int aw[2];
    uint32_t sBase[2];
#pragma unroll
    for (int i = 0; i < 2; i++) {
        int idx = tid + 256 * i;
        int m = idx >> 2, kq = idx & 3;
        int gm = bm + m; if (gm > M - 1) gm = M - 1;
        aOff[i] = (size_t)gm * K + 4 * kq;
        aw[i] = ((m >> 4) * 2 + (kq >> 1)) * 140 + (kq & 1) * 68 + ((m >> 3) & 1) + (m & 7) * 8;
        (void)sBase;
    }
    size_t bOff[4]; int bw[4];
#pragma unroll
    for (int i = 0; i < 4; i++) {
        int idx = tid + 256 * i;
        int n = idx >> 2, kq = idx & 3;
        bOff[i] = (size_t)(bn + n) * K + 4 * kq;
        bw[i] = 2240 + n * 20 + 4 * kq;
    }

    float4 av[2], bv[4];
    // prologue: chunk 0
#pragma unroll
    for (int i = 0; i < 2; i++) av[i] = *(const float4*)&A[aOff[i]];
#pragma unroll
    for (int i = 0; i < 4; i++) bv[i] = *(const float4*)&Bw[bOff[i]];
#pragma unroll
    for (int i = 0; i < 2; i++) {
        sm[aw[i] + 0] = f2tf32(av[i].x); sm[aw[i] + 2] = f2tf32(av[i].y);
        sm[aw[i] + 4] = f2tf32(av[i].z); sm[aw[i] + 6] = f2tf32(av[i].w);
    }
#pragma unroll
    for (int i = 0; i < 4; i++) {
        uint4 u; u.x = f2tf32(bv[i].x); u.y = f2tf32(bv[i].y);
        u.z = f2tf32(bv[i].z); u.w = f2tf32(bv[i].w);
        *(uint4*)&sm[bw[i]] = u;
    }
    __syncthreads();

    float acc[4][8][4];
#pragma unroll
    for (int mi = 0; mi < 4; mi++)
#pragma unroll
        for (int nj = 0; nj < 8; nj++)
#pragma unroll
            for (int c = 0; c < 4; c++) acc[mi][nj][c] = 0.f;

    for (int kt = 0; kt < KT; kt++) {
        const uint32_t buf = (kt & 1) * GBUF;
        if (kt + 1 < KT) {
            size_t ko = (size_t)((kt + 1) << 4);
#pragma unroll
            for (int i = 0; i < 2; i++) av[i] = *(const float4*)&A[aOff[i] + ko];
#pragma unroll
            for (int i = 0; i < 4; i++) bv[i] = *(const float4*)&Bw[bOff[i] + ko];
        }
#pragma unroll
        for (int s = 0; s < 2; s++) {
            uint32_t a[4][4];
#pragma unroll
            for (int mi = 0; mi < 4; mi++) {
                uint32_t t0 = buf + ((wm * 4 + mi) * 2 + s) * 140 + lane * 2;
                uint2 p0 = *(const uint2*)&sm[t0];
                uint2 p1 = *(const uint2*)&sm[t0 + 68];
                a[mi][0] = p0.x; a[mi][1] = p0.y; a[mi][2] = p1.x; a[mi][3] = p1.y;
            }
            uint32_t b[8][2];
#pragma unroll
            for (int nj = 0; nj < 8; nj++) {
                uint32_t t0 = buf + 2240 + (wn * 64 + nj * 8 + gid) * 20 + s * 8 + tig;
                b[nj][0] = sm[t0];
                b[nj][1] = sm[t0 + 4];
            }
#pragma unroll
            for (int mi = 0; mi < 4; mi++)
#pragma unroll
                for (int nj = 0; nj < 8; nj++) {
                    asm volatile(
                        "mma.sync.aligned.m16n8k8.row.col.f32.tf32.tf32.f32 "
                        "{%0,%1,%2,%3}, {%4,%5,%6,%7}, {%8,%9}, {%0,%1,%2,%3};"
                        : "+f"(acc[mi][nj][0]), "+f"(acc[mi][nj][1]),
                          "+f"(acc[mi][nj][2]), "+f"(acc[mi][nj][3])
                        : "r"(a[mi][0]), "r"(a[mi][1]), "r"(a[mi][2]), "r"(a[mi][3]),
                          "r"(b[nj][0]), "r"(b[nj][1]));
                }
        }
        if (kt + 1 < KT) {
            const uint32_t nb = ((kt + 1) & 1) * GBUF;
#pragma unroll
            for (int i = 0; i < 2; i++) {
                sm[nb + aw[i] + 0] = f2tf32(av[i].x); sm[nb + aw[i] + 2] = f2tf32(av[i].y);
                sm[nb + aw[i] + 4] = f2tf32(av[i].z); sm[nb + aw[i] + 6] = f2tf32(av[i].w);
            }
#pragma unroll
            for (int i = 0; i < 4; i++) {
                uint4 u; u.x = f2tf32(bv[i].x); u.y = f2tf32(bv[i].y);
                u.z = f2tf32(bv[i].z); u.w = f2tf32(bv[i].w);
                *(uint4*)&sm[nb + bw[i]] = u;
            }
            __syncthreads();
        }
    }

    // ---- epilogue ----
    const int m_base = bm + wm * 64;
    const int n_base = bn + wn * 64;
#pragma unroll
    for (int mi = 0; mi < 4; mi++) {
        int r0 = m_base + mi * 16 + gid;
        int r1 = r0 + 8;
#pragma unroll
        for (int nj = 0; nj < 8; nj++) {
            int col = n_base + nj * 8 + 2 * tig;
            float2 v0 = make_float2(acc[mi][nj][0], acc[mi][nj][1]);
            float2 v1 = make_float2(acc[mi][nj][2], acc[mi][nj][3]);
            if (bias) {
                float2 bb = *(const float2*)&bias[col];
                v0.x += bb.x; v0.y += bb.y; v1.x += bb.x; v1.y += bb.y;
            }
            if (r0 < M) {
                if (res) {
                    float2 rr = *(const float2*)&res[(size_t)r0 * N + col];
                    v0.x += rr.x; v0.y += rr.y;
                }
                if (GELU) {
                    v0.x = 0.5f * v0.x * (1.f + erff(v0.x * 0.70710678118654752f));
                    v0.y = 0.5f * v0.y * (1.f + erff(v0.y * 0.70710678118654752f));
                }
                *(float2*)&C[(size_t)r0 * N + col] = v0;
            }
            if (r1 < M) {
                if (res) {
                    float2 rr = *(const float2*)&res[(size_t)r1 * N + col];
                    v1.x += rr.x; v1.y += rr.y;
                }
                if (GELU) {
                    v1.x = 0.5f * v1.x * (1.f + erff(v1.x * 0.70710678118654752f));
                    v1.y = 0.5f * v1.y * (1.f + erff(v1.y * 0.70710678118654752f));
                }
                *(float2*)&C[(size_t)r1 * N + col] = v1;
            }
        }
    }
}

// ---------------- exact fp32 GEMM (64x64 tile) for the metric path ----------------
__global__ void gemm64_kernel(const float* __restrict__ A, const float* __restrict__ Bw,
                              float* __restrict__ C, int M, int N, int K) {
    __shared__ float As[16][65];
    __shared__ float Bs[16][65];
    int tid = threadIdx.x;
    int tx = tid & 15, ty = tid >> 4;
    int bm = blockIdx.y * 64, bn = blockIdx.x * 64;
    const float* Ab = A  + (size_t)bm * K;
    const float* Bb = Bw + (size_t)bn * K;
    float acc[4][4] = {};
    for (int k0 = 0; k0 < K; k0 += 16) {
#pragma unroll
        for (int r = 0; r < 4; r++) {
            int row = ty + r * 16;
            As[tx][row] = Ab[(size_t)row * K + k0 + tx];
            Bs[tx][row] = Bb[(size_t)row * K + k0 + tx];
        }
        __syncthreads();
#pragma unroll
        for (int kk = 0; kk < 16; kk++) {
            float a[4], b[4];
#pragma unroll
            for (int i = 0; i < 4; i++) a[i] = As[kk][ty * 4 + i];
#pragma unroll
            for (int j = 0; j < 4; j++) b[j] = Bs[kk][tx * 4 + j];
#pragma unroll
            for (int i = 0; i < 4; i++)
#pragma unroll
                for (int j = 0; j < 4; j++) acc[i][j] += a[i] * b[j];
        }
        __syncthreads();
    }
#pragma unroll
    for (int i = 0; i < 4; i++) {
        int m = bm + ty * 4 + i;
#pragma unroll
        for (int j = 0; j < 4; j++) {
            int n = bn + tx * 4 + j;
            C[(size_t)m * N + n] = acc[i][j];
        }
    }
}

// ---------------- W_avg = mean over heads of w_k rows ----------------
__global__ void wavg_kernel(const float* __restrict__ w_qkv) {
    int i = blockIdx.x * blockDim.x + threadIdx.x;
    if (i >= HD * DIMM) return;
    int d = i / DIMM, c = i % DIMM;
    float s = 0.f;
#pragma unroll
    for (int h = 0; h < HEADS; h++)
        s += w_qkv[(size_t)(DIMM + h * HD + d) * DIMM + c];
    g_wavg[i] = s * (1.f / (float)HEADS);
}

// ---------------- attention: one block per (b,h), 8 warps ----------------
#define KVP 68
#define ATTN_SMEM ((TT * KVP * 2 + 8 * 64 + 8 * TT + TT) * 4)
__global__ void attn_kernel(const float* __restrict__ attn_size) {
    extern __shared__ float smf[];
    float* Ks = smf;
    float* Vs = Ks + TT * KVP;
    float* qs = Vs + TT * KVP;
    float* ps = qs + 8 * 64;
    float* Ls = ps + 8 * TT;
    int bh = blockIdx.x;
    int b = bh / HEADS, h = bh % HEADS;
    int tid = threadIdx.x, w = tid >> 5, l = tid & 31;

    for (int idx = tid; idx < TT * HD; idx += 256) {
        int j = idx >> 6, d = idx & 63;
        const float* base = g_qkv + (size_t)(b * TT + j) * (3 * DIMM) + h * HD + d;
        Ks[j * KVP + d] = base[DIMM];
        Vs[j * KVP + d] = base[2 * DIMM];
    }
    for (int j = tid; j < TT; j += 256) Ls[j] = logf(attn_size[b * TT + j]);
    __syncthreads();

    const float scale = 0.125f;
    for (int i = w; i < TT; i += 8) {
        const float* qp = g_qkv + (size_t)(b * TT + i) * (3 * DIMM) + h * HD;
        qs[w * 64 + l]      = qp[l];
        qs[w * 64 + l + 32] = qp[l + 32];
        __syncwarp();
        const float4* q4 = (const float4*)&qs[w * 64];
        float sreg[7];
        float mx = -INFINITY;
        int cnt = 0;
        for (int j = l; j < TT; j += 32, cnt++) {
            const float4* k4 = (const float4*)&Ks[j * KVP];
            float s = 0.f;
#pragma unroll
            for (int d4 = 0; d4 < 16; d4++) {
                float4 kv = k4[d4], qv = q4[d4];
                s += qv.x * kv.x + qv.y * kv.y + qv.z * kv.z + qv.w * kv.w;
            }
            s = s * scale + Ls[j];
            sreg[cnt] = s;
            mx = fmaxf(mx, s);
        }
#pragma unroll
        for (int off = 16; off; off >>= 1) mx = fmaxf(mx, __shfl_xor_sync(0xffffffffu, mx, off));
        float sum = 0.f;
        cnt = 0;
        for (int j = l; j < TT; j += 32, cnt++) {
            float e = expf(sreg[cnt] - mx);
            sreg[cnt] = e;
            sum += e;
        }
#pragma unroll
        for (int off = 16; off; off >>= 1) sum += __shfl_xor_sync(0xffffffffu, sum, off);
        float inv = 1.f / sum;
        cnt = 0;
        for (int j = l; j < TT; j += 32, cnt++) ps[w * TT + j] = sreg[cnt] * inv;
        __syncwarp();
#pragma unroll
        for (int dd = 0; dd < 2; dd++) {
            int d = l + dd * 32;
            float acc = 0.f;
            int j = 0;
            for (; j + 4 <= TT; j += 4) {
                acc += ps[w * TT + j + 0] * Vs[(j + 0) * KVP + d];
                acc += ps[w * TT + j + 1] * Vs[(j + 1) * KVP + d];
                acc += ps[w * TT + j + 2] * Vs[(j + 2) * KVP + d];
                acc += ps[w * TT + j + 3] * Vs[(j + 3) * KVP + d];
            }
            for (; j < TT; j++) acc += ps[w * TT + j] * Vs[j * KVP + d];
            g_o[(size_t)(b * TT + i) * DIMM + h * HD + d] = acc;
        }
        __syncwarp();
    }
}

// ---------------- matching: one block per batch ----------------
#define MATCH_SMEM (TT * 65 * 4)
__global__ void match_kernel(const float* __restrict__ attn_size, float* __restrict__ rci_out) {
    extern __shared__ float m_s[];
    __shared__ float node_max[TE];
    __shared__ int   node_idx[TE];
    __shared__ int   rank_s[TE];
    __shared__ int   rowmap_s[TE];
    __shared__ float sizes_s[TN];
    int b = blockIdx.x;
    int tid = threadIdx.x, w = tid >> 5, l = tid & 31;

    for (int t = w; t < TT; t += 8) {
        float v0 = g_met[(size_t)(b * TT + t) * HD + l];
        float v1 = g_met[(size_t)(b * TT + t) * HD + l + 32];
        float ss = v0 * v0 + v1 * v1;
#pragma unroll
        for (int off = 16; off; off >>= 1) ss += __shfl_xor_sync(0xffffffffu, ss, off);
        float nrm = sqrtf(ss);
        m_s[t * 65 + l]      = v0 / nrm;
        m_s[t * 65 + l + 32] = v1 / nrm;
    }
    __syncthreads();

    for (int i = w; i < TE; i += 8) {
        float bm = -INFINITY; int bi = 0;
        if (i != 0) {
            for (int j = l; j < TO; j += 32) {
                float s = 0.f;
#pragma unroll
                for (int d = 0; d < HD; d++) s += m_s[(2 * i) * 65 + d] * m_s[(2 * j + 1) * 65 + d];
                if (s > bm) { bm = s; bi = j; }
            }
        }
#pragma unroll
        for (int off = 16; off; off >>= 1) {
            float om = __shfl_xor_sync(0xffffffffu, bm, off);
            int   oi = __shfl_xor_sync(0xffffffffu, bi, off);
            if (om > bm || (om == bm && oi < bi)) { bm = om; bi = oi; }
        }
        if (l == 0) { node_max[i] = bm; node_idx[i] = bi; }
    }
    __syncthreads();

    if (tid < TE) {
        float v = node_max[tid];
        int c = 0;
        for (int j = 0; j < TE; j++) {
            float u = node_max[j];
            if (u > v || (u == v && j < tid)) c++;
        }
        rank_s[tid] = c;
    }
    __syncthreads();

    if (tid < TE) {
        int row;
        if (rank_s[tid] >= R_EFF) {
            int c = 0;
            for (int j = 0; j < tid; j++) if (rank_s[j] >= R_EFF) c++;
            row = c;
        } else {
            row = UNM + node_idx[tid];
        }
        rowmap_s[tid] = row;
        g_rowmap[b * TE + tid] = row;
    }
    for (int r = tid; r < TN; r += 256) sizes_s[r] = 0.f;
    __syncthreads();

    for (int t = tid; t < TT; t += 256) {
        int row = (t & 1) ? (UNM + (t >> 1)) : rowmap_s[t >> 1];
        atomicAdd(&sizes_s[row], attn_size[b * TT + t]);
        if (t >= 1) rci_out[(size_t)b * (TT - 1) + (t - 1)] = (float)(row - 1);
    }
    __syncthreads();
    for (int r = tid; r < TN; r += 256) g_nsz[b * TN + r] = sizes_s[r];
}

// ---------------- merge ----------------
__global__ void zero_x2() {
    int i = blockIdx.x * blockDim.x + threadIdx.x;
    if (i < BTN * DIMM) g_x2[i] = 0.f;
}

__global__ void merge_kernel(const float* __restrict__ attn_size) {
    int bt = blockIdx.x;
    int b = bt / TT, t = bt % TT;
    int row = (t & 1) ? (UNM + (t >> 1)) : g_rowmap[b * TE + (t >> 1)];
    float s = attn_size[bt];
    const float* src = g_x1 + (size_t)bt * DIMM;
    float* dst = g_x2 + ((size_t)b * TN + row) * DIMM;
    for (int d = threadIdx.x; d < DIMM; d += 256) atomicAdd(&dst[d], src[d] * s);
}

__global__ void finalize_kernel(float* __restrict__ out_ns) {
    int br = blockIdx.x;
    float ns = g_nsz[br];
    if (threadIdx.x == 0) out_ns[br] = ns;
    float* p = g_x2 + (size_t)br * DIMM;
    for (int d = threadIdx.x; d < DIMM; d += 256) p[d] = p[d] / ns;
}

// ---------------- launch ----------------
extern "C" void kernel_launch(void* const* d_in, const int* in_sizes, int n_in,
                              void* d_out, int out_size) {
    const float* x         = (const float*)d_in[0];
    const float* attn_size = (const float*)d_in[1];
    const float* ln1_g     = (const float*)d_in[2];
    const float* ln1_b     = (const float*)d_in[3];
    const float* w_qkv     = (const float*)d_in[4];
    const float* w_proj    = (const float*)d_in[5];
    const float* b_proj    = (const float*)d_in[6];
    const float* ln2_g     = (const float*)d_in[7];
    const float* ln2_b     = (const float*)d_in[8];
    const float* w_fc1     = (const float*)d_in[9];
    const float* b_fc1     = (const float*)d_in[10];
    const float* w_fc2     = (const float*)d_in[11];
    const float* b_fc2     = (const float*)d_in[12];

    float* out_x   = (float*)d_out;
    float* out_ns  = out_x + (size_t)BTN * DIMM;
    float* out_rci = out_ns + BTN;

    cudaFuncSetAttribute(attn_kernel, cudaFuncAttributeMaxDynamicSharedMemorySize, ATTN_SMEM);
    cudaFuncSetAttribute(match_kernel, cudaFuncAttributeMaxDynamicSharedMemorySize, MATCH_SMEM);
    cudaFuncSetAttribute(mma_gemm<false>, cudaFuncAttributeMaxDynamicSharedMemorySize, GSMEM_BYTES);
    cudaFuncSetAttribute(mma_gemm<true>,  cudaFuncAttributeMaxDynamicSharedMemorySize, GSMEM_BYTES);

    float *g_h_p, *g_o_p, *g_x2_p, *g_h2_p, *g_g_p, *g_qkv_p, *g_x1_p, *g_met_p, *g_wavg_p;
    cudaGetSymbolAddress((void**)&g_h_p,  g_h);
    cudaGetSymbolAddress((void**)&g_o_p,  g_o);
    cudaGetSymbolAddress((void**)&g_x2_p, g_x2);
    cudaGetSymbolAddress((void**)&g_h2_p, g_h2);
    cudaGetSymbolAddress((void**)&g_g_p,  g_g);
    cudaGetSymbolAddress((void**)&g_qkv_p, g_qkv);
    cudaGetSymbolAddress((void**)&g_x1_p, g_x1);
    cudaGetSymbolAddress((void**)&g_met_p, g_met);
    cudaGetSymbolAddress((void**)&g_wavg_p, g_wavg);

    // 1) LN1
    ln_kernel<<<BT, 256>>>(x, ln1_g, ln1_b, g_h_p);
    // 2) qkv (tf32 tensor cores)
    mma_gemm<false><<<dim3(3 * DIMM / 256, (BT + 127) / 128), 256, GSMEM_BYTES>>>(
        g_h_p, w_qkv, nullptr, nullptr, g_qkv_p, BT, 3 * DIMM, DIMM);
    // 3) attention
    attn_kernel<<<BB * HEADS, 256, ATTN_SMEM>>>(attn_size);
    // 4) x1 = x + o @ w_proj^T + b_proj (tf32)
    mma_gemm<false><<<dim3(DIMM / 256, (BT + 127) / 128), 256, GSMEM_BYTES>>>(
        g_o_p, w_proj, b_proj, x, g_x1_p, BT, DIMM, DIMM);
    // 5) metric = h @ W_avg^T (exact fp32 — correctness-critical matching path)
    wavg_kernel<<<(HD * DIMM + 255) / 256, 256>>>(w_qkv);
    gemm64_kernel<<<dim3(1, BT / 64), 256>>>(g_h_p, g_wavg_p, g_met_p, BT, HD, DIMM);
    // 6) matching
    match_kernel<<<BB, 256, MATCH_SMEM>>>(attn_size, out_rci);
    // 7-9) merge
    zero_x2<<<(BTN * DIMM + 255) / 256, 256>>>();
    merge_kernel<<<BT, 256>>>(attn_size);
    finalize_kernel<<<BTN, 256>>>(out_ns);
    // 10) LN2
    ln_kernel<<<BTN, 256>>>(g_x2_p, ln2_g, ln2_b, g_h2_p);
    // 11) MLP (tf32)
    mma_gemm<true><<<dim3(MLP_H / 256, (BTN + 127) / 128), 256, GSMEM_BYTES>>>(
        g_h2_p, w_fc1, b_fc1, nullptr, g_g_p, BTN, MLP_H, DIMM);
    mma_gemm<false><<<dim3(DIMM / 256, (BTN + 127) / 128), 256, GSMEM_BYTES>>>(
        g_g_p, w_fc2, b_fc2, g_x2_p, out_x, BTN, DIMM, MLP_H);
}

// round 4
// speedup vs baseline: 2.9876x; 1.0725x over previous
#include <cuda_runtime.h>
#include <math.h>
#include <stdint.h>

// ---------------- problem constants ----------------
#define BB     64
#define TT     197
#define DIMM   768
#define HEADS  12
#define HD     64
#define MLP_H  3072
#define R_EFF  16
#define TE     99
#define TO     98
#define UNM    (TE - R_EFF)  // 83
#define TN     (UNM + TO)    // 181
#define BT     (BB * TT)     // 12608
#define BTN    (BB * TN)     // 11584
#define LNEPS  1e-5f

// ---------------- scratch ----------------
__device__ float g_h   [BT  * DIMM];
__device__ float g_qkv [BT  * 3 * DIMM];
__device__ float g_o   [BT  * DIMM];
__device__ float g_x1  [BT  * DIMM];
__device__ float g_met [BT  * HD];
__device__ float g_wavg[HD * DIMM];
__device__ int   g_rowmap[BB * TE];
__device__ float g_nsz [BB * TN];
__device__ float g_x2  [BTN * DIMM];
__device__ float g_h2  [BTN * DIMM];
__device__ float g_g   [BTN * MLP_H];

// ---------------- layernorm ----------------
__global__ void ln_kernel(const float* __restrict__ x, const float* __restrict__ gam,
                          const float* __restrict__ bet, float* __restrict__ out) {
    int t = blockIdx.x;
    const float* p = x + (size_t)t * DIMM;
    int tid = threadIdx.x;
    float v[3]; float s = 0.f, ss = 0.f;
#pragma unroll
    for (int r = 0; r < 3; r++) { v[r] = p[tid + r * 256]; s += v[r]; ss += v[r] * v[r]; }
#pragma unroll
    for (int off = 16; off; off >>= 1) {
        s  += __shfl_xor_sync(0xffffffffu, s,  off);
        ss += __shfl_xor_sync(0xffffffffu, ss, off);
    }
    __shared__ float sm_s[8], sm_ss[8];
    if ((tid & 31) == 0) { sm_s[tid >> 5] = s; sm_ss[tid >> 5] = ss; }
    __syncthreads();
    if (tid < 32) {
        s  = (tid < 8) ? sm_s[tid]  : 0.f;
        ss = (tid < 8) ? sm_ss[tid] : 0.f;
#pragma unroll
        for (int off = 4; off; off >>= 1) {
            s  += __shfl_xor_sync(0xffffffffu, s,  off);
            ss += __shfl_xor_sync(0xffffffffu, ss, off);
        }
        if (tid == 0) { sm_s[0] = s; sm_ss[0] = ss; }
    }
    __syncthreads();
    float mean = sm_s[0] * (1.f / (float)DIMM);
    float var  = sm_ss[0] * (1.f / (float)DIMM) - mean * mean;
    float rs = rsqrtf(var + LNEPS);
    float* po = out + (size_t)t * DIMM;
#pragma unroll
    for (int r = 0; r < 3; r++) {
        int d = tid + r * 256;
        po[d] = (v[r] - mean) * rs * gam[d] + bet[d];
    }
}

// =====================================================================
// tf32 tensor-core GEMM, cp.async 3-stage pipeline.
// C = A[M,K] * B[N,K]^T (+bias)(+res)(gelu)
// BM=128, BN=256, BK=16, 256 threads (8 warps, 2x4, 64x64 warp tile).
// N % 256 == 0, K % 16 == 0, M arbitrary. fp32 fed raw to tf32 mma
// (hardware truncation — CUTLASS fast path).
// smem per stage (words): A [128][20] = 2560, B [256][20] = 5120 -> 7680
// 3 stages = 23040 words = 92160 bytes.
// =====================================================================
#define SSTR 7680
#define GSMEM_BYTES (3 * SSTR * 4)

__device__ __forceinline__ void cp16(uint32_t s, const void* g) {
    asm volatile("cp.async.cg.shared.global [%0], [%1], 16;\n" :: "r"(s), "l"(g));
}

template <bool GELU>
__global__ void __launch_bounds__(256) mma_gemm(
    const float* __restrict__ A, const float* __restrict__ Bw,
    const float* __restrict__ bias, const float* __restrict__ res,
    float* __restrict__ C, int M, int N, int K)
{
    extern __shared__ float smf[];
    const uint32_t smb = (uint32_t)__cvta_generic_to_shared(smf);
    const int tid = threadIdx.x;
    const int lane = tid & 31, w = tid >> 5;
    const int wm = w >> 2, wn = w & 3;
    const int gid = lane >> 2, tig = lane & 3;
    const int bm = blockIdx.y * 128, bn = blockIdx.x * 256;
    const int KT = K >> 4;

    // staging: A 2 chunks/thread, B 4 chunks/thread (16B each)
    size_t aOff[2]; uint32_t aw[2];
#pragma unroll
    for (int i = 0; i < 2; i++) {
        int idx = tid + 256 * i;
        int m = idx >> 2, kq = idx & 3;
        int gm = bm + m; if (gm > M - 1) gm = M - 1;
        aOff[i] = (size_t)gm * K + 4 * kq;
        aw[i]   = (uint32_t)(m * 20 + kq * 4) * 4;
    }
    size_t bOff[4]; uint32_t bw[4];
#pragma unroll
    for (int i = 0; i < 4; i++) {
        int idx = tid + 256 * i;
        int n = idx >> 2, kq = idx & 3;
        bOff[i] = (size_t)(bn + n) * K + 4 * kq;
        bw[i]   = (uint32_t)(2560 + n * 20 + kq * 4) * 4;
    }

    // prologue: stages 0..2 (KT >= 3 always here)
#pragma unroll
    for (int st = 0; st < 3; st++) {
        uint32_t sb = smb + st * SSTR * 4;
        size_t ko = (size_t)(st << 4);
#pragma unroll
        for (int i = 0; i < 2; i++) cp16(sb + aw[i], &A[aOff[i] + ko]);
#pragma unroll
        for (int i = 0; i < 4; i++) cp16(sb + bw[i], &Bw[bOff[i] + ko]);
        asm volatile("cp.async.commit_group;\n" ::);
    }

    float acc[4][8][4];
#pragma unroll
    for (int mi = 0; mi < 4; mi++)
#pragma unroll
        for (int nj = 0; nj < 8; nj++)
#pragma unroll
            for (int c = 0; c < 4; c++) acc[mi][nj][c] = 0.f;

    int stage = 0;
    for (int kt = 0; kt < KT; kt++) {
        asm volatile("cp.async.wait_group 2;\n" ::);
        __syncthreads();
        const float* buf = smf + stage * SSTR;
        const float* Asm = buf;
        const float* Bsm = buf + 2560;
#pragma unroll
        for (int s = 0; s < 2; s++) {
            uint32_t a[4][4];
#pragma unroll
            for (int mi = 0; mi < 4; mi++) {
                int m0 = wm * 64 + mi * 16 + gid;
                int k0 = s * 8 + tig;
                a[mi][0] = __float_as_uint(Asm[(m0    ) * 20 + k0    ]);
                a[mi][1] = __float_as_uint(Asm[(m0 + 8) * 20 + k0    ]);
                a[mi][2] = __float_as_uint(Asm[(m0    ) * 20 + k0 + 4]);
                a[mi][3] = __float_as_uint(Asm[(m0 + 8) * 20 + k0 + 4]);
            }
            uint32_t b[8][2];
#pragma unroll
            for (int nj = 0; nj < 8; nj++) {
                int n0 = wn * 64 + nj * 8 + gid;
                int k0 = s * 8 + tig;
                b[nj][0] = __float_as_uint(Bsm[n0 * 20 + k0    ]);
                b[nj][1] = __float_as_uint(Bsm[n0 * 20 + k0 + 4]);
            }
#pragma unroll
            for (int mi = 0; mi < 4; mi++)
#pragma unroll
                for (int nj = 0; nj < 8; nj++) {
                    asm volatile(
                        "mma.sync.aligned.m16n8k8.row.col.f32.tf32.tf32.f32 "
                        "{%0,%1,%2,%3}, {%4,%5,%6,%7}, {%8,%9}, {%0,%1,%2,%3};"
                        : "+f"(acc[mi][nj][0]), "+f"(acc[mi][nj][1]),
                          "+f"(acc[mi][nj][2]), "+f"(acc[mi][nj][3])
                        : "r"(a[mi][0]), "r"(a[mi][1]), "r"(a[mi][2]), "r"(a[mi][3]),
                          "r"(b[nj][0]), "r"(b[nj][1]));
                }
        }
        __syncthreads();
        int kn = kt + 3;
        if (kn < KT) {
            uint32_t sb = smb + stage * SSTR * 4;
            size_t ko = (size_t)(kn << 4);
#pragma unroll
            for (int i = 0; i < 2; i++) cp16(sb + aw[i], &A[aOff[i] + ko]);
#pragma unroll
            for (int i = 0; i < 4; i++) cp16(sb + bw[i], &Bw[bOff[i] + ko]);
        }
        asm volatile("cp.async.commit_group;\n" ::);
        stage = (stage + 1 == 3) ? 0 : stage + 1;
    }

    // ---- epilogue ----
    const int m_base = bm + wm * 64;
    const int n_base = bn + wn * 64;
#pragma unroll
    for (int mi = 0; mi < 4; mi++) {
        int r0 = m_base + mi * 16 + gid;
        int r1 = r0 + 8;
#pragma unroll
        for (int nj = 0; nj < 8; nj++) {
            int col = n_base + nj * 8 + 2 * tig;
            float2 v0 = make_float2(acc[mi][nj][0], acc[mi][nj][1]);
            float2 v1 = make_float2(acc[mi][nj][2], acc[mi][nj][3]);
            if (bias) {
                float2 bb = *(const float2*)&bias[col];
                v0.x += bb.x; v0.y += bb.y; v1.x += bb.x; v1.y += bb.y;
            }
            if (r0 < M) {
                if (res) {
                    float2 rr = *(const float2*)&res[(size_t)r0 * N + col];
                    v0.x += rr.x; v0.y += rr.y;
                }
                if (GELU) {
                    v0.x = 0.5f * v0.x * (1.f + erff(v0.x * 0.70710678118654752f));
                    v0.y = 0.5f * v0.y * (1.f + erff(v0.y * 0.70710678118654752f));
                }
                *(float2*)&C[(size_t)r0 * N + col] = v0;
            }
            if (r1 < M) {
                if (res) {
                    float2 rr = *(const float2*)&res[(size_t)r1 * N + col];
                    v1.x += rr.x; v1.y += rr.y;
                }
                if (GELU) {
                    v1.x = 0.5f * v1.x * (1.f + erff(v1.x * 0.70710678118654752f));
                    v1.y = 0.5f * v1.y * (1.f + erff(v1.y * 0.70710678118654752f));
                }
                *(float2*)&C[(size_t)r1 * N + col] = v1;
            }
        }
    }
}

// ---------------- exact fp32 GEMM (64x64 tile) for the metric path ----------------
__global__ void gemm64_kernel(const float* __restrict__ A, const float* __restrict__ Bw,
                              float* __restrict__ C, int M, int N, int K) {
    __shared__ float As[16][65];
    __shared__ float Bs[16][65];
    int tid = threadIdx.x;
    int tx = tid & 15, ty = tid >> 4;
    int bm = blockIdx.y * 64, bn = blockIdx.x * 64;
    const float* Ab = A  + (size_t)bm * K;
    const float* Bb = Bw + (size_t)bn * K;
    float acc[4][4] = {};
    for (int k0 = 0; k0 < K; k0 += 16) {
#pragma unroll
        for (int r = 0; r < 4; r++) {
            int row = ty + r * 16;
            As[tx][row] = Ab[(size_t)row * K + k0 + tx];
            Bs[tx][row] = Bb[(size_t)row * K + k0 + tx];
        }
        __syncthreads();
#pragma unroll
        for (int kk = 0; kk < 16; kk++) {
            float a[4], b[4];
#pragma unroll
            for (int i = 0; i < 4; i++) a[i] = As[kk][ty * 4 + i];
#pragma unroll
            for (int j = 0; j < 4; j++) b[j] = Bs[kk][tx * 4 + j];
#pragma unroll
            for (int i = 0; i < 4; i++)
#pragma unroll
                for (int j = 0; j < 4; j++) acc[i][j] += a[i] * b[j];
        }
        __syncthreads();
    }
#pragma unroll
    for (int i = 0; i < 4; i++) {
        int m = bm + ty * 4 + i;
#pragma unroll
        for (int j = 0; j < 4; j++) {
            int n = bn + tx * 4 + j;
            C[(size_t)m * N + n] = acc[i][j];
        }
    }
}

// ---------------- W_avg = mean over heads of w_k rows ----------------
__global__ void wavg_kernel(const float* __restrict__ w_qkv) {
    int i = blockIdx.x * blockDim.x + threadIdx.x;
    if (i >= HD * DIMM) return;
    int d = i / DIMM, c = i % DIMM;
    float s = 0.f;
#pragma unroll
    for (int h = 0; h < HEADS; h++)
        s += w_qkv[(size_t)(DIMM + h * HD + d) * DIMM + c];
    g_wavg[i] = s * (1.f / (float)HEADS);
}

// ---------------- attention: one block per (b,h), 8 warps ----------------
#define KVP 68
#define ATTN_SMEM ((TT * KVP * 2 + 8 * 64 + 8 * TT + TT) * 4)
__global__ void attn_kernel(const float* __restrict__ attn_size) {
    extern __shared__ float smf[];
    float* Ks = smf;
    float* Vs = Ks + TT * KVP;
    float* qs = Vs + TT * KVP;
    float* ps = qs + 8 * 64;
    float* Ls = ps + 8 * TT;
    int bh = blockIdx.x;
    int b = bh / HEADS, h = bh % HEADS;
    int tid = threadIdx.x, w = tid >> 5, l = tid & 31;

    for (int idx = tid; idx < TT * HD; idx += 256) {
        int j = idx >> 6, d = idx & 63;
        const float* base = g_qkv + (size_t)(b * TT + j) * (3 * DIMM) + h * HD + d;
        Ks[j * KVP + d] = base[DIMM];
        Vs[j * KVP + d] = base[2 * DIMM];
    }
    for (int j = tid; j < TT; j += 256) Ls[j] = logf(attn_size[b * TT + j]);
    __syncthreads();

    const float scale = 0.125f;
    for (int i = w; i < TT; i += 8) {
        const float* qp = g_qkv + (size_t)(b * TT + i) * (3 * DIMM) + h * HD;
        qs[w * 64 + l]      = qp[l];
        qs[w * 64 + l + 32] = qp[l + 32];
        __syncwarp();
        const float4* q4 = (const float4*)&qs[w * 64];
        float sreg[7];
        float mx = -INFINITY;
        int cnt = 0;
        for (int j = l; j < TT; j += 32, cnt++) {
            const float4* k4 = (const float4*)&Ks[j * KVP];
            float s = 0.f;
#pragma unroll
            for (int d4 = 0; d4 < 16; d4++) {
                float4 kv = k4[d4], qv = q4[d4];
                s += qv.x * kv.x + qv.y * kv.y + qv.z * kv.z + qv.w * kv.w;
            }
            s = s * scale + Ls[j];
            sreg[cnt] = s;
            mx = fmaxf(mx, s);
        }
#pragma unroll
        for (int off = 16; off; off >>= 1) mx = fmaxf(mx, __shfl_xor_sync(0xffffffffu, mx, off));
        float sum = 0.f;
        cnt = 0;
        for (int j = l; j < TT; j += 32, cnt++) {
            float e = expf(sreg[cnt] - mx);
            sreg[cnt] = e;
            sum += e;
        }
#pragma unroll
        for (int off = 16; off; off >>= 1) sum += __shfl_xor_sync(0xffffffffu, sum, off);
        float inv = 1.f / sum;
        cnt = 0;
        for (int j = l; j < TT; j += 32, cnt++) ps[w * TT + j] = sreg[cnt] * inv;
        __syncwarp();
#pragma unroll
        for (int dd = 0; dd < 2; dd++) {
            int d = l + dd * 32;
            float acc = 0.f;
            int j = 0;
            for (; j + 4 <= TT; j += 4) {
                acc += ps[w * TT + j + 0] * Vs[(j + 0) * KVP + d];
                acc += ps[w * TT + j + 1] * Vs[(j + 1) * KVP + d];
                acc += ps[w * TT + j + 2] * Vs[(j + 2) * KVP + d];
                acc += ps[w * TT + j + 3] * Vs[(j + 3) * KVP + d];
            }
            for (; j < TT; j++) acc += ps[w * TT + j] * Vs[j * KVP + d];
            g_o[(size_t)(b * TT + i) * DIMM + h * HD + d] = acc;
        }
        __syncwarp();
    }
}

// ---------------- matching: one block per batch ----------------
#define MATCH_SMEM (TT * 65 * 4)
__global__ void match_kernel(const float* __restrict__ attn_size, float* __restrict__ rci_out) {
    extern __shared__ float m_s[];
    __shared__ float node_max[TE];
    __shared__ int   node_idx[TE];
    __shared__ int   rank_s[TE];
    __shared__ int   rowmap_s[TE];
    __shared__ float sizes_s[TN];
    int b = blockIdx.x;
    int tid = threadIdx.x, w = tid >> 5, l = tid & 31;

    for (int t = w; t < TT; t += 8) {
        float v0 = g_met[(size_t)(b * TT + t) * HD + l];
        float v1 = g_met[(size_t)(b * TT + t) * HD + l + 32];
        float ss = v0 * v0 + v1 * v1;
#pragma unroll
        for (int off = 16; off; off >>= 1) ss += __shfl_xor_sync(0xffffffffu, ss, off);
        float nrm = sqrtf(ss);
        m_s[t * 65 + l]      = v0 / nrm;
        m_s[t * 65 + l + 32] = v1 / nrm;
    }
    __syncthreads();

    for (int i = w; i < TE; i += 8) {
        float bm = -INFINITY; int bi = 0;
        if (i != 0) {
            for (int j = l; j < TO; j += 32) {
                float s = 0.f;
#pragma unroll
                for (int d = 0; d < HD; d++) s += m_s[(2 * i) * 65 + d] * m_s[(2 * j + 1) * 65 + d];
                if (s > bm) { bm = s; bi = j; }
            }
        }
#pragma unroll
        for (int off = 16; off; off >>= 1) {
            float om = __shfl_xor_sync(0xffffffffu, bm, off);
            int   oi = __shfl_xor_sync(0xffffffffu, bi, off);
            if (om > bm || (om == bm && oi < bi)) { bm = om; bi = oi; }
        }
        if (l == 0) { node_max[i] = bm; node_idx[i] = bi; }
    }
    __syncthreads();

    if (tid < TE) {
        float v = node_max[tid];
        int c = 0;
        for (int j = 0; j < TE; j++) {
            float u = node_max[j];
            if (u > v || (u == v && j < tid)) c++;
        }
        rank_s[tid] = c;
    }
    __syncthreads();

    if (tid < TE) {
        int row;
        if (rank_s[tid] >= R_EFF) {
            int c = 0;
            for (int j = 0; j < tid; j++) if (rank_s[j] >= R_EFF) c++;
            row = c;
        } else {
            row = UNM + node_idx[tid];
        }
        rowmap_s[tid] = row;
        g_rowmap[b * TE + tid] = row;
    }
    for (int r = tid; r < TN; r += 256) sizes_s[r] = 0.f;
    __syncthreads();

    for (int t = tid; t < TT; t += 256) {
        int row = (t & 1) ? (UNM + (t >> 1)) : rowmap_s[t >> 1];
        atomicAdd(&sizes_s[row], attn_size[b * TT + t]);
        if (t >= 1) rci_out[(size_t)b * (TT - 1) + (t - 1)] = (float)(row - 1);
    }
    __syncthreads();
    for (int r = tid; r < TN; r += 256) g_nsz[b * TN + r] = sizes_s[r];
}

// ---------------- merge ----------------
__global__ void zero_x2() {
    int i = blockIdx.x * blockDim.x + threadIdx.x;
    if (i < BTN * DIMM) g_x2[i] = 0.f;
}

__global__ void merge_kernel(const float* __restrict__ attn_size) {
    int bt = blockIdx.x;
    int b = bt / TT, t = bt % TT;
    int row = (t & 1) ? (UNM + (t >> 1)) : g_rowmap[b * TE + (t >> 1)];
    float s = attn_size[bt];
    const float* src = g_x1 + (size_t)bt * DIMM;
    float* dst = g_x2 + ((size_t)b * TN + row) * DIMM;
    for (int d = threadIdx.x; d < DIMM; d += 256) atomicAdd(&dst[d], src[d] * s);
}

__global__ void finalize_kernel(float* __restrict__ out_ns) {
    int br = blockIdx.x;
    float ns = g_nsz[br];
    if (threadIdx.x == 0) out_ns[br] = ns;
    float* p = g_x2 + (size_t)br * DIMM;
    for (int d = threadIdx.x; d < DIMM; d += 256) p[d] = p[d] / ns;
}

// ---------------- launch ----------------
extern "C" void kernel_launch(void* const* d_in, const int* in_sizes, int n_in,
                              void* d_out, int out_size) {
    const float* x         = (const float*)d_in[0];
    const float* attn_size = (const float*)d_in[1];
    const float* ln1_g     = (const float*)d_in[2];
    const float* ln1_b     = (const float*)d_in[3];
    const float* w_qkv     = (const float*)d_in[4];
    const float* w_proj    = (const float*)d_in[5];
    const float* b_proj    = (const float*)d_in[6];
    const float* ln2_g     = (const float*)d_in[7];
    const float* ln2_b     = (const float*)d_in[8];
    const float* w_fc1     = (const float*)d_in[9];
    const float* b_fc1     = (const float*)d_in[10];
    const float* w_fc2     = (const float*)d_in[11];
    const float* b_fc2     = (const float*)d_in[12];

    float* out_x   = (float*)d_out;
    float* out_ns  = out_x + (size_t)BTN * DIMM;
    float* out_rci = out_ns + BTN;

    cudaFuncSetAttribute(attn_kernel, cudaFuncAttributeMaxDynamicSharedMemorySize, ATTN_SMEM);
    cudaFuncSetAttribute(match_kernel, cudaFuncAttributeMaxDynamicSharedMemorySize, MATCH_SMEM);
    cudaFuncSetAttribute(mma_gemm<false>, cudaFuncAttributeMaxDynamicSharedMemorySize, GSMEM_BYTES);
    cudaFuncSetAttribute(mma_gemm<true>,  cudaFuncAttributeMaxDynamicSharedMemorySize, GSMEM_BYTES);

    float *g_h_p, *g_o_p, *g_x2_p, *g_h2_p, *g_g_p, *g_qkv_p, *g_x1_p, *g_met_p, *g_wavg_p;
    cudaGetSymbolAddress((void**)&g_h_p,  g_h);
    cudaGetSymbolAddress((void**)&g_o_p,  g_o);
    cudaGetSymbolAddress((void**)&g_x2_p, g_x2);
    cudaGetSymbolAddress((void**)&g_h2_p, g_h2);
    cudaGetSymbolAddress((void**)&g_g_p,  g_g);
    cudaGetSymbolAddress((void**)&g_qkv_p, g_qkv);
    cudaGetSymbolAddress((void**)&g_x1_p, g_x1);
    cudaGetSymbolAddress((void**)&g_met_p, g_met);
    cudaGetSymbolAddress((void**)&g_wavg_p, g_wavg);

    // 1) LN1
    ln_kernel<<<BT, 256>>>(x, ln1_g, ln1_b, g_h_p);
    // 2) qkv (tf32 tensor cores)
    mma_gemm<false><<<dim3(3 * DIMM / 256, (BT + 127) / 128), 256, GSMEM_BYTES>>>(
        g_h_p, w_qkv, nullptr, nullptr, g_qkv_p, BT, 3 * DIMM, DIMM);
    // 3) attention
    attn_kernel<<<BB * HEADS, 256, ATTN_SMEM>>>(attn_size);
    // 4) x1 = x + o @ w_proj^T + b_proj (tf32)
    mma_gemm<false><<<dim3(DIMM / 256, (BT + 127) / 128), 256, GSMEM_BYTES>>>(
        g_o_p, w_proj, b_proj, x, g_x1_p, BT, DIMM, DIMM);
    // 5) metric = h @ W_avg^T (exact fp32 — correctness-critical matching path)
    wavg_kernel<<<(HD * DIMM + 255) / 256, 256>>>(w_qkv);
    gemm64_kernel<<<dim3(1, BT / 64), 256>>>(g_h_p, g_wavg_p, g_met_p, BT, HD, DIMM);
    // 6) matching
    match_kernel<<<BB, 256, MATCH_SMEM>>>(attn_size, out_rci);
    // 7-9) merge
    zero_x2<<<(BTN * DIMM + 255) / 256, 256>>>();
    merge_kernel<<<BT, 256>>>(attn_size);
    finalize_kernel<<<BTN, 256>>>(out_ns);
    // 10) LN2
    ln_kernel<<<BTN, 256>>>(g_x2_p, ln2_g, ln2_b, g_h2_p);
    // 11) MLP (tf32)
    mma_gemm<true><<<dim3(MLP_H / 256, (BTN + 127) / 128), 256, GSMEM_BYTES>>>(
        g_h2_p, w_fc1, b_fc1, nullptr, g_g_p, BTN, MLP_H, DIMM);
    mma_gemm<false><<<dim3(DIMM / 256, (BTN + 127) / 128), 256, GSMEM_BYTES>>>(
        g_g_p, w_fc2, b_fc2, g_x2_p, out_x, BTN, DIMM, MLP_H);
}

// round 5
// speedup vs baseline: 3.2101x; 1.0745x over previous
#include <cuda_runtime.h>
#include <math.h>
#include <stdint.h>

// ---------------- problem constants ----------------
#define BB     64
#define TT     197
#define DIMM   768
#define HEADS  12
#define HD     64
#define MLP_H  3072
#define R_EFF  16
#define TE     99
#define TO     98
#define UNM    (TE - R_EFF)  // 83
#define TN     (UNM + TO)    // 181
#define BT     (BB * TT)     // 12608
#define BTN    (BB * TN)     // 11584
#define LNEPS  1e-5f

// ---------------- scratch ----------------
__device__ float g_h   [BT  * DIMM];
__device__ float g_qkv [BT  * 3 * DIMM];
__device__ float g_o   [BT  * DIMM];
__device__ float g_x1  [BT  * DIMM];
__device__ float g_met [BT  * HD];
__device__ float g_wavg[HD * DIMM];
__device__ int   g_rowmap[BB * TE];
__device__ float g_nsz [BB * TN];
__device__ float g_x2  [BTN * DIMM];
__device__ float g_h2  [BTN * DIMM];
__device__ float g_g   [BTN * MLP_H];

// ---------------- layernorm ----------------
__global__ void ln_kernel(const float* __restrict__ x, const float* __restrict__ gam,
                          const float* __restrict__ bet, float* __restrict__ out) {
    int t = blockIdx.x;
    const float* p = x + (size_t)t * DIMM;
    int tid = threadIdx.x;
    float v[3]; float s = 0.f, ss = 0.f;
#pragma unroll
    for (int r = 0; r < 3; r++) { v[r] = p[tid + r * 256]; s += v[r]; ss += v[r] * v[r]; }
#pragma unroll
    for (int off = 16; off; off >>= 1) {
        s  += __shfl_xor_sync(0xffffffffu, s,  off);
        ss += __shfl_xor_sync(0xffffffffu, ss, off);
    }
    __shared__ float sm_s[8], sm_ss[8];
    if ((tid & 31) == 0) { sm_s[tid >> 5] = s; sm_ss[tid >> 5] = ss; }
    __syncthreads();
    if (tid < 32) {
        s  = (tid < 8) ? sm_s[tid]  : 0.f;
        ss = (tid < 8) ? sm_ss[tid] : 0.f;
#pragma unroll
        for (int off = 4; off; off >>= 1) {
            s  += __shfl_xor_sync(0xffffffffu, s,  off);
            ss += __shfl_xor_sync(0xffffffffu, ss, off);
        }
        if (tid == 0) { sm_s[0] = s; sm_ss[0] = ss; }
    }
    __syncthreads();
    float mean = sm_s[0] * (1.f / (float)DIMM);
    float var  = sm_ss[0] * (1.f / (float)DIMM) - mean * mean;
    float rs = rsqrtf(var + LNEPS);
    float* po = out + (size_t)t * DIMM;
#pragma unroll
    for (int r = 0; r < 3; r++) {
        int d = tid + r * 256;
        po[d] = (v[r] - mean) * rs * gam[d] + bet[d];
    }
}

// =====================================================================
// tf32 tensor-core GEMM, cp.async 4-stage pipeline, 2 CTAs/SM.
// C = A[M,K] * B[N,K]^T (+bias)(+res)(gelu)
// BM=128, BN=128, BK=16, 256 threads (8 warps 2x4, 64x32 warp tile).
// N % 128 == 0, K % 16 == 0 (KT >= 4), M arbitrary.
// stage: A [128][20] + B [128][20] = 5120 words = 20 KB; 4 stages = 80 KB.
// One __syncthreads per k-step (prefetch depth 3 writes the slot consumed
// in the previous iteration; the sync orders it).
// =====================================================================
#define SSTR 5120
#define NSTG 4
#define GSMEM_BYTES (NSTG * SSTR * 4)

__device__ __forceinline__ void cp16(uint32_t s, const void* g) {
    asm volatile("cp.async.cg.shared.global [%0], [%1], 16;\n" :: "r"(s), "l"(g));
}

template <bool GELU>
__global__ void __launch_bounds__(256, 2) mma_gemm(
    const float* __restrict__ A, const float* __restrict__ Bw,
    const float* __restrict__ bias, const float* __restrict__ res,
    float* __restrict__ C, int M, int N, int K)
{
    extern __shared__ float smf[];
    const uint32_t smb = (uint32_t)__cvta_generic_to_shared(smf);
    const int tid = threadIdx.x;
    const int lane = tid & 31, w = tid >> 5;
    const int wm = w >> 2, wn = w & 3;
    const int gid = lane >> 2, tig = lane & 3;
    const int bm = blockIdx.y * 128, bn = blockIdx.x * 128;
    const int KT = K >> 4;

    // staging: A 2 chunks/thread, B 2 chunks/thread (16B each)
    size_t aOff[2]; uint32_t aw[2];
    size_t bOff[2]; uint32_t bw[2];
#pragma unroll
    for (int i = 0; i < 2; i++) {
        int idx = tid + 256 * i;
        int m = idx >> 2, kq = idx & 3;
        int gm = bm + m; if (gm > M - 1) gm = M - 1;
        aOff[i] = (size_t)gm * K + 4 * kq;
        aw[i]   = (uint32_t)(m * 20 + kq * 4) * 4;
        bOff[i] = (size_t)(bn + m) * K + 4 * kq;
        bw[i]   = (uint32_t)(2560 + m * 20 + kq * 4) * 4;
    }

    // prologue: stages 0..2
#pragma unroll
    for (int st = 0; st < NSTG - 1; st++) {
        uint32_t sb = smb + st * SSTR * 4;
        size_t ko = (size_t)(st << 4);
#pragma unroll
        for (int i = 0; i < 2; i++) cp16(sb + aw[i], &A[aOff[i] + ko]);
#pragma unroll
        for (int i = 0; i < 2; i++) cp16(sb + bw[i], &Bw[bOff[i] + ko]);
        asm volatile("cp.async.commit_group;\n" ::);
    }

    float acc[4][4][4];
#pragma unroll
    for (int mi = 0; mi < 4; mi++)
#pragma unroll
        for (int nj = 0; nj < 4; nj++)
#pragma unroll
            for (int c = 0; c < 4; c++) acc[mi][nj][c] = 0.f;

    for (int kt = 0; kt < KT; kt++) {
        asm volatile("cp.async.wait_group %0;\n" :: "n"(NSTG - 2));
        __syncthreads();
        // prefetch stage kt+3 into slot (kt-1)%4 (consumed last iteration)
        int kn = kt + NSTG - 1;
        if (kn < KT) {
            uint32_t sb = smb + (kn & (NSTG - 1)) * SSTR * 4;
            size_t ko = (size_t)(kn << 4);
#pragma unroll
            for (int i = 0; i < 2; i++) cp16(sb + aw[i], &A[aOff[i] + ko]);
#pragma unroll
            for (int i = 0; i < 2; i++) cp16(sb + bw[i], &Bw[bOff[i] + ko]);
        }
        asm volatile("cp.async.commit_group;\n" ::);

        const float* buf = smf + (kt & (NSTG - 1)) * SSTR;
        const float* Asm = buf;
        const float* Bsm = buf + 2560;
#pragma unroll
        for (int s = 0; s < 2; s++) {
            const int k0 = s * 8 + tig;
            uint32_t a[4][4];
#pragma unroll
            for (int mi = 0; mi < 4; mi++) {
                int m0 = wm * 64 + mi * 16 + gid;
                a[mi][0] = __float_as_uint(Asm[(m0    ) * 20 + k0    ]);
                a[mi][1] = __float_as_uint(Asm[(m0 + 8) * 20 + k0    ]);
                a[mi][2] = __float_as_uint(Asm[(m0    ) * 20 + k0 + 4]);
                a[mi][3] = __float_as_uint(Asm[(m0 + 8) * 20 + k0 + 4]);
            }
            uint32_t b[4][2];
#pragma unroll
            for (int nj = 0; nj < 4; nj++) {
                int n0 = wn * 32 + nj * 8 + gid;
                b[nj][0] = __float_as_uint(Bsm[n0 * 20 + k0    ]);
                b[nj][1] = __float_as_uint(Bsm[n0 * 20 + k0 + 4]);
            }
#pragma unroll
            for (int mi = 0; mi < 4; mi++)
#pragma unroll
                for (int nj = 0; nj < 4; nj++) {
                    asm volatile(
                        "mma.sync.aligned.m16n8k8.row.col.f32.tf32.tf32.f32 "
                        "{%0,%1,%2,%3}, {%4,%5,%6,%7}, {%8,%9}, {%0,%1,%2,%3};"
                        : "+f"(acc[mi][nj][0]), "+f"(acc[mi][nj][1]),
                          "+f"(acc[mi][nj][2]), "+f"(acc[mi][nj][3])
                        : "r"(a[mi][0]), "r"(a[mi][1]), "r"(a[mi][2]), "r"(a[mi][3]),
                          "r"(b[nj][0]), "r"(b[nj][1]));
                }
        }
    }

    // ---- epilogue ----
    const int m_base = bm + wm * 64;
    const int n_base = bn + wn * 32;
#pragma unroll
    for (int mi = 0; mi < 4; mi++) {
        int r0 = m_base + mi * 16 + gid;
        int r1 = r0 + 8;
#pragma unroll
        for (int nj = 0; nj < 4; nj++) {
            int col = n_base + nj * 8 + 2 * tig;
            float2 v0 = make_float2(acc[mi][nj][0], acc[mi][nj][1]);
            float2 v1 = make_float2(acc[mi][nj][2], acc[mi][nj][3]);
            if (bias) {
                float2 bb = *(const float2*)&bias[col];
                v0.x += bb.x; v0.y += bb.y; v1.x += bb.x; v1.y += bb.y;
            }
            if (r0 < M) {
                if (res) {
                    float2 rr = *(const float2*)&res[(size_t)r0 * N + col];
                    v0.x += rr.x; v0.y += rr.y;
                }
                if (GELU) {
                    v0.x = 0.5f * v0.x * (1.f + erff(v0.x * 0.70710678118654752f));
                    v0.y = 0.5f * v0.y * (1.f + erff(v0.y * 0.70710678118654752f));
                }
                *(float2*)&C[(size_t)r0 * N + col] = v0;
            }
            if (r1 < M) {
                if (res) {
                    float2 rr = *(const float2*)&res[(size_t)r1 * N + col];
                    v1.x += rr.x; v1.y += rr.y;
                }
                if (GELU) {
                    v1.x = 0.5f * v1.x * (1.f + erff(v1.x * 0.70710678118654752f));
                    v1.y = 0.5f * v1.y * (1.f + erff(v1.y * 0.70710678118654752f));
                }
                *(float2*)&C[(size_t)r1 * N + col] = v1;
            }
        }
    }
}

// ---------------- exact fp32 GEMM (64x64 tile) for the metric path ----------------
__global__ void gemm64_kernel(const float* __restrict__ A, const float* __restrict__ Bw,
                              float* __restrict__ C, int M, int N, int K) {
    __shared__ float As[16][65];
    __shared__ float Bs[16][65];
    int tid = threadIdx.x;
    int tx = tid & 15, ty = tid >> 4;
    int bm = blockIdx.y * 64, bn = blockIdx.x * 64;
    const float* Ab = A  + (size_t)bm * K;
    const float* Bb = Bw + (size_t)bn * K;
    float acc[4][4] = {};
    for (int k0 = 0; k0 < K; k0 += 16) {
#pragma unroll
        for (int r = 0; r < 4; r++) {
            int row = ty + r * 16;
            As[tx][row] = Ab[(size_t)row * K + k0 + tx];
            Bs[tx][row] = Bb[(size_t)row * K + k0 + tx];
        }
        __syncthreads();
#pragma unroll
        for (int kk = 0; kk < 16; kk++) {
            float a[4], b[4];
#pragma unroll
            for (int i = 0; i < 4; i++) a[i] = As[kk][ty * 4 + i];
#pragma unroll
            for (int j = 0; j < 4; j++) b[j] = Bs[kk][tx * 4 + j];
#pragma unroll
            for (int i = 0; i < 4; i++)
#pragma unroll
                for (int j = 0; j < 4; j++) acc[i][j] += a[i] * b[j];
        }
        __syncthreads();
    }
#pragma unroll
    for (int i = 0; i < 4; i++) {
        int m = bm + ty * 4 + i;
#pragma unroll
        for (int j = 0; j < 4; j++) {
            int n = bn + tx * 4 + j;
            C[(size_t)m * N + n] = acc[i][j];
        }
    }
}

// ---------------- W_avg = mean over heads of w_k rows ----------------
__global__ void wavg_kernel(const float* __restrict__ w_qkv) {
    int i = blockIdx.x * blockDim.x + threadIdx.x;
    if (i >= HD * DIMM) return;
    int d = i / DIMM, c = i % DIMM;
    float s = 0.f;
#pragma unroll
    for (int h = 0; h < HEADS; h++)
        s += w_qkv[(size_t)(DIMM + h * HD + d) * DIMM + c];
    g_wavg[i] = s * (1.f / (float)HEADS);
}

// ---------------- attention: one block per (b,h), 8 warps ----------------
#define KVP 68
#define ATTN_SMEM ((TT * KVP * 2 + 8 * 64 + 8 * TT + TT) * 4)
__global__ void attn_kernel(const float* __restrict__ attn_size) {
    extern __shared__ float smf[];
    float* Ks = smf;
    float* Vs = Ks + TT * KVP;
    float* qs = Vs + TT * KVP;
    float* ps = qs + 8 * 64;
    float* Ls = ps + 8 * TT;
    int bh = blockIdx.x;
    int b = bh / HEADS, h = bh % HEADS;
    int tid = threadIdx.x, w = tid >> 5, l = tid & 31;

    for (int idx = tid; idx < TT * HD; idx += 256) {
        int j = idx >> 6, d = idx & 63;
        const float* base = g_qkv + (size_t)(b * TT + j) * (3 * DIMM) + h * HD + d;
        Ks[j * KVP + d] = base[DIMM];
        Vs[j * KVP + d] = base[2 * DIMM];
    }
    for (int j = tid; j < TT; j += 256) Ls[j] = logf(attn_size[b * TT + j]);
    __syncthreads();

    const float scale = 0.125f;
    for (int i = w; i < TT; i += 8) {
        const float* qp = g_qkv + (size_t)(b * TT + i) * (3 * DIMM) + h * HD;
        qs[w * 64 + l]      = qp[l];
        qs[w * 64 + l + 32] = qp[l + 32];
        __syncwarp();
        const float4* q4 = (const float4*)&qs[w * 64];
        float sreg[7];
        float mx = -INFINITY;
        int cnt = 0;
        for (int j = l; j < TT; j += 32, cnt++) {
            const float4* k4 = (const float4*)&Ks[j * KVP];
            float s = 0.f;
#pragma unroll
            for (int d4 = 0; d4 < 16; d4++) {
                float4 kv = k4[d4], qv = q4[d4];
                s += qv.x * kv.x + qv.y * kv.y + qv.z * kv.z + qv.w * kv.w;
            }
            s = s * scale + Ls[j];
            sreg[cnt] = s;
            mx = fmaxf(mx, s);
        }
#pragma unroll
        for (int off = 16; off; off >>= 1) mx = fmaxf(mx, __shfl_xor_sync(0xffffffffu, mx, off));
        float sum = 0.f;
        cnt = 0;
        for (int j = l; j < TT; j += 32, cnt++) {
            float e = expf(sreg[cnt] - mx);
            sreg[cnt] = e;
            sum += e;
        }
#pragma unroll
        for (int off = 16; off; off >>= 1) sum += __shfl_xor_sync(0xffffffffu, sum, off);
        float inv = 1.f / sum;
        cnt = 0;
        for (int j = l; j < TT; j += 32, cnt++) ps[w * TT + j] = sreg[cnt] * inv;
        __syncwarp();
#pragma unroll
        for (int dd = 0; dd < 2; dd++) {
            int d = l + dd * 32;
            float acc = 0.f;
            int j = 0;
            for (; j + 4 <= TT; j += 4) {
                acc += ps[w * TT + j + 0] * Vs[(j + 0) * KVP + d];
                acc += ps[w * TT + j + 1] * Vs[(j + 1) * KVP + d];
                acc += ps[w * TT + j + 2] * Vs[(j + 2) * KVP + d];
                acc += ps[w * TT + j + 3] * Vs[(j + 3) * KVP + d];
            }
            for (; j < TT; j++) acc += ps[w * TT + j] * Vs[j * KVP + d];
            g_o[(size_t)(b * TT + i) * DIMM + h * HD + d] = acc;
        }
        __syncwarp();
    }
}

// ---------------- matching: one block per batch ----------------
#define MATCH_SMEM (TT * 65 * 4)
__global__ void match_kernel(const float* __restrict__ attn_size, float* __restrict__ rci_out) {
    extern __shared__ float m_s[];
    __shared__ float node_max[TE];
    __shared__ int   node_idx[TE];
    __shared__ int   rank_s[TE];
    __shared__ int   rowmap_s[TE];
    __shared__ float sizes_s[TN];
    int b = blockIdx.x;
    int tid = threadIdx.x, w = tid >> 5, l = tid & 31;

    for (int t = w; t < TT; t += 8) {
        float v0 = g_met[(size_t)(b * TT + t) * HD + l];
        float v1 = g_met[(size_t)(b * TT + t) * HD + l + 32];
        float ss = v0 * v0 + v1 * v1;
#pragma unroll
        for (int off = 16; off; off >>= 1) ss += __shfl_xor_sync(0xffffffffu, ss, off);
        float nrm = sqrtf(ss);
        m_s[t * 65 + l]      = v0 / nrm;
        m_s[t * 65 + l + 32] = v1 / nrm;
    }
    __syncthreads();

    for (int i = w; i < TE; i += 8) {
        float bm = -INFINITY; int bi = 0;
        if (i != 0) {
            for (int j = l; j < TO; j += 32) {
                float s = 0.f;
#pragma unroll
                for (int d = 0; d < HD; d++) s += m_s[(2 * i) * 65 + d] * m_s[(2 * j + 1) * 65 + d];
                if (s > bm) { bm = s; bi = j; }
            }
        }
#pragma unroll
        for (int off = 16; off; off >>= 1) {
            float om = __shfl_xor_sync(0xffffffffu, bm, off);
            int   oi = __shfl_xor_sync(0xffffffffu, bi, off);
            if (om > bm || (om == bm && oi < bi)) { bm = om; bi = oi; }
        }
        if (l == 0) { node_max[i] = bm; node_idx[i] = bi; }
    }
    __syncthreads();

    if (tid < TE) {
        float v = node_max[tid];
        int c = 0;
        for (int j = 0; j < TE; j++) {
            float u = node_max[j];
            if (u > v || (u == v && j < tid)) c++;
        }
        rank_s[tid] = c;
    }
    __syncthreads();

    if (tid < TE) {
        int row;
        if (rank_s[tid] >= R_EFF) {
            int c = 0;
            for (int j = 0; j < tid; j++) if (rank_s[j] >= R_EFF) c++;
            row = c;
        } else {
            row = UNM + node_idx[tid];
        }
        rowmap_s[tid] = row;
        g_rowmap[b * TE + tid] = row;
    }
    for (int r = tid; r < TN; r += 256) sizes_s[r] = 0.f;
    __syncthreads();

    for (int t = tid; t < TT; t += 256) {
        int row = (t & 1) ? (UNM + (t >> 1)) : rowmap_s[t >> 1];
        atomicAdd(&sizes_s[row], attn_size[b * TT + t]);
        if (t >= 1) rci_out[(size_t)b * (TT - 1) + (t - 1)] = (float)(row - 1);
    }
    __syncthreads();
    for (int r = tid; r < TN; r += 256) g_nsz[b * TN + r] = sizes_s[r];
}

// ---------------- merge ----------------
__global__ void zero_x2() {
    int i = blockIdx.x * blockDim.x + threadIdx.x;
    if (i < BTN * DIMM) g_x2[i] = 0.f;
}

__global__ void merge_kernel(const float* __restrict__ attn_size) {
    int bt = blockIdx.x;
    int b = bt / TT, t = bt % TT;
    int row = (t & 1) ? (UNM + (t >> 1)) : g_rowmap[b * TE + (t >> 1)];
    float s = attn_size[bt];
    const float* src = g_x1 + (size_t)bt * DIMM;
    float* dst = g_x2 + ((size_t)b * TN + row) * DIMM;
    for (int d = threadIdx.x; d < DIMM; d += 256) atomicAdd(&dst[d], src[d] * s);
}

__global__ void finalize_kernel(float* __restrict__ out_ns) {
    int br = blockIdx.x;
    float ns = g_nsz[br];
    if (threadIdx.x == 0) out_ns[br] = ns;
    float* p = g_x2 + (size_t)br * DIMM;
    for (int d = threadIdx.x; d < DIMM; d += 256) p[d] = p[d] / ns;
}

// ---------------- launch ----------------
extern "C" void kernel_launch(void* const* d_in, const int* in_sizes, int n_in,
                              void* d_out, int out_size) {
    const float* x         = (const float*)d_in[0];
    const float* attn_size = (const float*)d_in[1];
    const float* ln1_g     = (const float*)d_in[2];
    const float* ln1_b     = (const float*)d_in[3];
    const float* w_qkv     = (const float*)d_in[4];
    const float* w_proj    = (const float*)d_in[5];
    const float* b_proj    = (const float*)d_in[6];
    const float* ln2_g     = (const float*)d_in[7];
    const float* ln2_b     = (const float*)d_in[8];
    const float* w_fc1     = (const float*)d_in[9];
    const float* b_fc1     = (const float*)d_in[10];
    const float* w_fc2     = (const float*)d_in[11];
    const float* b_fc2     = (const float*)d_in[12];

    float* out_x   = (float*)d_out;
    float* out_ns  = out_x + (size_t)BTN * DIMM;
    float* out_rci = out_ns + BTN;

    cudaFuncSetAttribute(attn_kernel, cudaFuncAttributeMaxDynamicSharedMemorySize, ATTN_SMEM);
    cudaFuncSetAttribute(match_kernel, cudaFuncAttributeMaxDynamicSharedMemorySize, MATCH_SMEM);
    cudaFuncSetAttribute(mma_gemm<false>, cudaFuncAttributeMaxDynamicSharedMemorySize, GSMEM_BYTES);
    cudaFuncSetAttribute(mma_gemm<true>,  cudaFuncAttributeMaxDynamicSharedMemorySize, GSMEM_BYTES);

    float *g_h_p, *g_o_p, *g_x2_p, *g_h2_p, *g_g_p, *g_qkv_p, *g_x1_p, *g_met_p, *g_wavg_p;
    cudaGetSymbolAddress((void**)&g_h_p,  g_h);
    cudaGetSymbolAddress((void**)&g_o_p,  g_o);
    cudaGetSymbolAddress((void**)&g_x2_p, g_x2);
    cudaGetSymbolAddress((void**)&g_h2_p, g_h2);
    cudaGetSymbolAddress((void**)&g_g_p,  g_g);
    cudaGetSymbolAddress((void**)&g_qkv_p, g_qkv);
    cudaGetSymbolAddress((void**)&g_x1_p, g_x1);
    cudaGetSymbolAddress((void**)&g_met_p, g_met);
    cudaGetSymbolAddress((void**)&g_wavg_p, g_wavg);

    // 1) LN1
    ln_kernel<<<BT, 256>>>(x, ln1_g, ln1_b, g_h_p);
    // 2) qkv (tf32 tensor cores)
    mma_gemm<false><<<dim3(3 * DIMM / 128, (BT + 127) / 128), 256, GSMEM_BYTES>>>(
        g_h_p, w_qkv, nullptr, nullptr, g_qkv_p, BT, 3 * DIMM, DIMM);
    // 3) attention
    attn_kernel<<<BB * HEADS, 256, ATTN_SMEM>>>(attn_size);
    // 4) x1 = x + o @ w_proj^T + b_proj (tf32)
    mma_gemm<false><<<dim3(DIMM / 128, (BT + 127) / 128), 256, GSMEM_BYTES>>>(
        g_o_p, w_proj, b_proj, x, g_x1_p, BT, DIMM, DIMM);
    // 5) metric = h @ W_avg^T (exact fp32 — correctness-critical matching path)
    wavg_kernel<<<(HD * DIMM + 255) / 256, 256>>>(w_qkv);
    gemm64_kernel<<<dim3(1, BT / 64), 256>>>(g_h_p, g_wavg_p, g_met_p, BT, HD, DIMM);
    // 6) matching
    match_kernel<<<BB, 256, MATCH_SMEM>>>(attn_size, out_rci);
    // 7-9) merge
    zero_x2<<<(BTN * DIMM + 255) / 256, 256>>>();
    merge_kernel<<<BT, 256>>>(attn_size);
    finalize_kernel<<<BTN, 256>>>(out_ns);
    // 10) LN2
    ln_kernel<<<BTN, 256>>>(g_x2_p, ln2_g, ln2_b, g_h2_p);
    // 11) MLP (tf32)
    mma_gemm<true><<<dim3(MLP_H / 128, (BTN + 127) / 128), 256, GSMEM_BYTES>>>(
        g_h2_p, w_fc1, b_fc1, nullptr, g_g_p, BTN, MLP_H, DIMM);
    mma_gemm<false><<<dim3(DIMM / 128, (BTN + 127) / 128), 256, GSMEM_BYTES>>>(
        g_g_p, w_fc2, b_fc2, g_x2_p, out_x, BTN, DIMM, MLP_H);
}

// round 6
// speedup vs baseline: 3.3802x; 1.0530x over previous
#include <cuda_runtime.h>
#include <math.h>
#include <stdint.h>

// ---------------- problem constants ----------------
#define BB     64
#define TT     197
#define DIMM   768
#define HEADS  12
#define HD     64
#define MLP_H  3072
#define R_EFF  16
#define TE     99
#define TO     98
#define UNM    (TE - R_EFF)  // 83
#define TN     (UNM + TO)    // 181
#define BT     (BB * TT)     // 12608
#define BTN    (BB * TN)     // 11584
#define LNEPS  1e-5f

// ---------------- scratch ----------------
__device__ float g_h   [BT  * DIMM];
__device__ float g_qkv [BT  * 3 * DIMM];
__device__ float g_o   [BT  * DIMM];
__device__ float g_x1  [BT  * DIMM];
__device__ float g_met [BT  * HD];
__device__ float g_wavg[HD * DIMM];
__device__ int   g_rowmap[BB * TE];
__device__ float g_nsz [BB * TN];
__device__ float g_x2  [BTN * DIMM];
__device__ float g_h2  [BTN * DIMM];
__device__ float g_g   [BTN * MLP_H];

// ---------------- layernorm ----------------
__global__ void ln_kernel(const float* __restrict__ x, const float* __restrict__ gam,
                          const float* __restrict__ bet, float* __restrict__ out) {
    int t = blockIdx.x;
    const float* p = x + (size_t)t * DIMM;
    int tid = threadIdx.x;
    float v[3]; float s = 0.f, ss = 0.f;
#pragma unroll
    for (int r = 0; r < 3; r++) { v[r] = p[tid + r * 256]; s += v[r]; ss += v[r] * v[r]; }
#pragma unroll
    for (int off = 16; off; off >>= 1) {
        s  += __shfl_xor_sync(0xffffffffu, s,  off);
        ss += __shfl_xor_sync(0xffffffffu, ss, off);
    }
    __shared__ float sm_s[8], sm_ss[8];
    if ((tid & 31) == 0) { sm_s[tid >> 5] = s; sm_ss[tid >> 5] = ss; }
    __syncthreads();
    if (tid < 32) {
        s  = (tid < 8) ? sm_s[tid]  : 0.f;
        ss = (tid < 8) ? sm_ss[tid] : 0.f;
#pragma unroll
        for (int off = 4; off; off >>= 1) {
            s  += __shfl_xor_sync(0xffffffffu, s,  off);
            ss += __shfl_xor_sync(0xffffffffu, ss, off);
        }
        if (tid == 0) { sm_s[0] = s; sm_ss[0] = ss; }
    }
    __syncthreads();
    float mean = sm_s[0] * (1.f / (float)DIMM);
    float var  = sm_ss[0] * (1.f / (float)DIMM) - mean * mean;
    float rs = rsqrtf(var + LNEPS);
    float* po = out + (size_t)t * DIMM;
#pragma unroll
    for (int r = 0; r < 3; r++) {
        int d = tid + r * 256;
        po[d] = (v[r] - mean) * rs * gam[d] + bet[d];
    }
}

// =====================================================================
// tf32 tensor-core GEMM, cp.async 4-stage pipeline, 2 CTAs/SM,
// ldmatrix fragment loads.
// C = A[M,K] * B[N,K]^T (+bias)(+res)(gelu)
// BM=128, BN=128, BK=16, 256 threads (8 warps 2x4, 64x32 warp tile).
// N % 128 == 0, K % 16 == 0 (KT >= 4), M arbitrary.
// stage: A [128][20] + B [128][20] = 5120 words = 20 KB; 4 stages = 80 KB.
// Row stride 80 B => ldmatrix 8-row phases hit disjoint 16B segments
// (80*m mod 128 all distinct for m=0..7) — conflict-free.
// =====================================================================
#define SSTR 5120
#define NSTG 4
#define GSMEM_BYTES (NSTG * SSTR * 4)

__device__ __forceinline__ void cp16(uint32_t s, const void* g) {
    asm volatile("cp.async.cg.shared.global [%0], [%1], 16;\n" :: "r"(s), "l"(g));
}

template <bool GELU>
__global__ void __launch_bounds__(256, 2) mma_gemm(
    const float* __restrict__ A, const float* __restrict__ Bw,
    const float* __restrict__ bias, const float* __restrict__ res,
    float* __restrict__ C, int M, int N, int K)
{
    extern __shared__ float smf[];
    const uint32_t smb = (uint32_t)__cvta_generic_to_shared(smf);
    const int tid = threadIdx.x;
    const int lane = tid & 31, w = tid >> 5;
    const int wm = w >> 2, wn = w & 3;
    const int gid = lane >> 2, tig = lane & 3;
    const int bm = blockIdx.y * 128, bn = blockIdx.x * 128;
    const int KT = K >> 4;

    // staging: A 2 chunks/thread, B 2 chunks/thread (16B each)
    size_t aOff[2]; uint32_t aw[2];
    size_t bOff[2]; uint32_t bw[2];
#pragma unroll
    for (int i = 0; i < 2; i++) {
        int idx = tid + 256 * i;
        int m = idx >> 2, kq = idx & 3;
        int gm = bm + m; if (gm > M - 1) gm = M - 1;
        aOff[i] = (size_t)gm * K + 4 * kq;
        aw[i]   = (uint32_t)(m * 20 + kq * 4) * 4;
        bOff[i] = (size_t)(bn + m) * K + 4 * kq;
        bw[i]   = (uint32_t)(2560 + m * 20 + kq * 4) * 4;
    }

    // ldmatrix per-lane offsets (bytes within the A / B tile)
    // A x4: lanes 0-15 -> rows 0-15 @ k0, lanes 16-31 -> rows 0-15 @ k4
    const uint32_t aLM = (uint32_t)((lane & 15) * 80 + (lane >> 4) * 16);
    // B x2: lanes 0-7 -> rows @ k0, lanes 8-15 -> rows @ k4
    const uint32_t bLM = (uint32_t)((lane & 7) * 80 + ((lane >> 3) & 1) * 16);

    // prologue: stages 0..2
#pragma unroll
    for (int st = 0; st < NSTG - 1; st++) {
        uint32_t sb = smb + st * SSTR * 4;
        size_t ko = (size_t)(st << 4);
#pragma unroll
        for (int i = 0; i < 2; i++) cp16(sb + aw[i], &A[aOff[i] + ko]);
#pragma unroll
        for (int i = 0; i < 2; i++) cp16(sb + bw[i], &Bw[bOff[i] + ko]);
        asm volatile("cp.async.commit_group;\n" ::);
    }

    float acc[4][4][4];
#pragma unroll
    for (int mi = 0; mi < 4; mi++)
#pragma unroll
        for (int nj = 0; nj < 4; nj++)
#pragma unroll
            for (int c = 0; c < 4; c++) acc[mi][nj][c] = 0.f;

    for (int kt = 0; kt < KT; kt++) {
        asm volatile("cp.async.wait_group %0;\n" :: "n"(NSTG - 2));
        __syncthreads();
        // prefetch stage kt+3 into slot (kt-1)%4 (consumed last iteration)
        int kn = kt + NSTG - 1;
        if (kn < KT) {
            uint32_t sb = smb + (kn & (NSTG - 1)) * SSTR * 4;
            size_t ko = (size_t)(kn << 4);
#pragma unroll
            for (int i = 0; i < 2; i++) cp16(sb + aw[i], &A[aOff[i] + ko]);
#pragma unroll
            for (int i = 0; i < 2; i++) cp16(sb + bw[i], &Bw[bOff[i] + ko]);
        }
        asm volatile("cp.async.commit_group;\n" ::);

        const uint32_t sbase = smb + (kt & (NSTG - 1)) * SSTR * 4;
        const uint32_t aBase = sbase + (uint32_t)(wm * 64) * 80 + aLM;
        const uint32_t bBase = sbase + 10240u + (uint32_t)(wn * 32) * 80 + bLM;
#pragma unroll
        for (int s = 0; s < 2; s++) {
            uint32_t a[4][4];
#pragma unroll
            for (int mi = 0; mi < 4; mi++) {
                uint32_t ad = aBase + (uint32_t)(mi * 16 * 80 + s * 32);
                asm volatile(
                    "ldmatrix.sync.aligned.m8n8.x4.shared.b16 {%0,%1,%2,%3}, [%4];"
                    : "=r"(a[mi][0]), "=r"(a[mi][1]), "=r"(a[mi][2]), "=r"(a[mi][3])
                    : "r"(ad));
            }
            uint32_t b[4][2];
#pragma unroll
            for (int nj = 0; nj < 4; nj++) {
                uint32_t bd = bBase + (uint32_t)(nj * 8 * 80 + s * 32);
                asm volatile(
                    "ldmatrix.sync.aligned.m8n8.x2.shared.b16 {%0,%1}, [%2];"
                    : "=r"(b[nj][0]), "=r"(b[nj][1])
                    : "r"(bd));
            }
#pragma unroll
            for (int mi = 0; mi < 4; mi++)
#pragma unroll
                for (int nj = 0; nj < 4; nj++) {
                    asm volatile(
                        "mma.sync.aligned.m16n8k8.row.col.f32.tf32.tf32.f32 "
                        "{%0,%1,%2,%3}, {%4,%5,%6,%7}, {%8,%9}, {%0,%1,%2,%3};"
                        : "+f"(acc[mi][nj][0]), "+f"(acc[mi][nj][1]),
                          "+f"(acc[mi][nj][2]), "+f"(acc[mi][nj][3])
                        : "r"(a[mi][0]), "r"(a[mi][1]), "r"(a[mi][2]), "r"(a[mi][3]),
                          "r"(b[nj][0]), "r"(b[nj][1]));
                }
        }
    }

    // ---- epilogue ----
    const int m_base = bm + wm * 64;
    const int n_base = bn + wn * 32;
#pragma unroll
    for (int mi = 0; mi < 4; mi++) {
        int r0 = m_base + mi * 16 + gid;
        int r1 = r0 + 8;
#pragma unroll
        for (int nj = 0; nj < 4; nj++) {
            int col = n_base + nj * 8 + 2 * tig;
            float2 v0 = make_float2(acc[mi][nj][0], acc[mi][nj][1]);
            float2 v1 = make_float2(acc[mi][nj][2], acc[mi][nj][3]);
            if (bias) {
                float2 bb = *(const float2*)&bias[col];
                v0.x += bb.x; v0.y += bb.y; v1.x += bb.x; v1.y += bb.y;
            }
            if (r0 < M) {
                if (res) {
                    float2 rr = *(const float2*)&res[(size_t)r0 * N + col];
                    v0.x += rr.x; v0.y += rr.y;
                }
                if (GELU) {
                    v0.x = 0.5f * v0.x * (1.f + erff(v0.x * 0.70710678118654752f));
                    v0.y = 0.5f * v0.y * (1.f + erff(v0.y * 0.70710678118654752f));
                }
                *(float2*)&C[(size_t)r0 * N + col] = v0;
            }
            if (r1 < M) {
                if (res) {
                    float2 rr = *(const float2*)&res[(size_t)r1 * N + col];
                    v1.x += rr.x; v1.y += rr.y;
                }
                if (GELU) {
                    v1.x = 0.5f * v1.x * (1.f + erff(v1.x * 0.70710678118654752f));
                    v1.y = 0.5f * v1.y * (1.f + erff(v1.y * 0.70710678118654752f));
                }
                *(float2*)&C[(size_t)r1 * N + col] = v1;
            }
        }
    }
}

// ---------------- exact fp32 GEMM (64x64 tile) for the metric path ----------------
__global__ void gemm64_kernel(const float* __restrict__ A, const float* __restrict__ Bw,
                              float* __restrict__ C, int M, int N, int K) {
    __shared__ float As[16][65];
    __shared__ float Bs[16][65];
    int tid = threadIdx.x;
    int tx = tid & 15, ty = tid >> 4;
    int bm = blockIdx.y * 64, bn = blockIdx.x * 64;
    const float* Ab = A  + (size_t)bm * K;
    const float* Bb = Bw + (size_t)bn * K;
    float acc[4][4] = {};
    for (int k0 = 0; k0 < K; k0 += 16) {
#pragma unroll
        for (int r = 0; r < 4; r++) {
            int row = ty + r * 16;
            As[tx][row] = Ab[(size_t)row * K + k0 + tx];
            Bs[tx][row] = Bb[(size_t)row * K + k0 + tx];
        }
        __syncthreads();
#pragma unroll
        for (int kk = 0; kk < 16; kk++) {
            float a[4], b[4];
#pragma unroll
            for (int i = 0; i < 4; i++) a[i] = As[kk][ty * 4 + i];
#pragma unroll
            for (int j = 0; j < 4; j++) b[j] = Bs[kk][tx * 4 + j];
#pragma unroll
            for (int i = 0; i < 4; i++)
#pragma unroll
                for (int j = 0; j < 4; j++) acc[i][j] += a[i] * b[j];
        }
        __syncthreads();
    }
#pragma unroll
    for (int i = 0; i < 4; i++) {
        int m = bm + ty * 4 + i;
#pragma unroll
        for (int j = 0; j < 4; j++) {
            int n = bn + tx * 4 + j;
            C[(size_t)m * N + n] = acc[i][j];
        }
    }
}

// ---------------- W_avg = mean over heads of w_k rows ----------------
__global__ void wavg_kernel(const float* __restrict__ w_qkv) {
    int i = blockIdx.x * blockDim.x + threadIdx.x;
    if (i >= HD * DIMM) return;
    int d = i / DIMM, c = i % DIMM;
    float s = 0.f;
#pragma unroll
    for (int h = 0; h < HEADS; h++)
        s += w_qkv[(size_t)(DIMM + h * HD + d) * DIMM + c];
    g_wavg[i] = s * (1.f / (float)HEADS);
}

// ---------------- attention: one block per (b,h), 8 warps ----------------
#define KVP 68
#define ATTN_SMEM ((TT * KVP * 2 + 8 * 64 + 8 * TT + TT) * 4)
__global__ void attn_kernel(const float* __restrict__ attn_size) {
    extern __shared__ float smf[];
    float* Ks = smf;
    float* Vs = Ks + TT * KVP;
    float* qs = Vs + TT * KVP;
    float* ps = qs + 8 * 64;
    float* Ls = ps + 8 * TT;
    int bh = blockIdx.x;
    int b = bh / HEADS, h = bh % HEADS;
    int tid = threadIdx.x, w = tid >> 5, l = tid & 31;

    for (int idx = tid; idx < TT * HD; idx += 256) {
        int j = idx >> 6, d = idx & 63;
        const float* base = g_qkv + (size_t)(b * TT + j) * (3 * DIMM) + h * HD + d;
        Ks[j * KVP + d] = base[DIMM];
        Vs[j * KVP + d] = base[2 * DIMM];
    }
    for (int j = tid; j < TT; j += 256) Ls[j] = logf(attn_size[b * TT + j]);
    __syncthreads();

    const float scale = 0.125f;
    for (int i = w; i < TT; i += 8) {
        const float* qp = g_qkv + (size_t)(b * TT + i) * (3 * DIMM) + h * HD;
        qs[w * 64 + l]      = qp[l];
        qs[w * 64 + l + 32] = qp[l + 32];
        __syncwarp();
        const float4* q4 = (const float4*)&qs[w * 64];
        float sreg[7];
        float mx = -INFINITY;
        int cnt = 0;
        for (int j = l; j < TT; j += 32, cnt++) {
            const float4* k4 = (const float4*)&Ks[j * KVP];
            float s = 0.f;
#pragma unroll
            for (int d4 = 0; d4 < 16; d4++) {
                float4 kv = k4[d4], qv = q4[d4];
                s += qv.x * kv.x + qv.y * kv.y + qv.z * kv.z + qv.w * kv.w;
            }
            s = s * scale + Ls[j];
            sreg[cnt] = s;
            mx = fmaxf(mx, s);
        }
#pragma unroll
        for (int off = 16; off; off >>= 1) mx = fmaxf(mx, __shfl_xor_sync(0xffffffffu, mx, off));
        float sum = 0.f;
        cnt = 0;
        for (int j = l; j < TT; j += 32, cnt++) {
            float e = expf(sreg[cnt] - mx);
            sreg[cnt] = e;
            sum += e;
        }
#pragma unroll
        for (int off = 16; off; off >>= 1) sum += __shfl_xor_sync(0xffffffffu, sum, off);
        float inv = 1.f / sum;
        cnt = 0;
        for (int j = l; j < TT; j += 32, cnt++) ps[w * TT + j] = sreg[cnt] * inv;
        __syncwarp();
#pragma unroll
        for (int dd = 0; dd < 2; dd++) {
            int d = l + dd * 32;
            float acc = 0.f;
            int j = 0;
            for (; j + 4 <= TT; j += 4) {
                acc += ps[w * TT + j + 0] * Vs[(j + 0) * KVP + d];
                acc += ps[w * TT + j + 1] * Vs[(j + 1) * KVP + d];
                acc += ps[w * TT + j + 2] * Vs[(j + 2) * KVP + d];
                acc += ps[w * TT + j + 3] * Vs[(j + 3) * KVP + d];
            }
            for (; j < TT; j++) acc += ps[w * TT + j] * Vs[j * KVP + d];
            g_o[(size_t)(b * TT + i) * DIMM + h * HD + d] = acc;
        }
        __syncwarp();
    }
}

// ---------------- matching: one block per batch ----------------
#define MATCH_SMEM (TT * 65 * 4)
__global__ void match_kernel(const float* __restrict__ attn_size, float* __restrict__ rci_out) {
    extern __shared__ float m_s[];
    __shared__ float node_max[TE];
    __shared__ int   node_idx[TE];
    __shared__ int   rank_s[TE];
    __shared__ int   rowmap_s[TE];
    __shared__ float sizes_s[TN];
    int b = blockIdx.x;
    int tid = threadIdx.x, w = tid >> 5, l = tid & 31;

    for (int t = w; t < TT; t += 8) {
        float v0 = g_met[(size_t)(b * TT + t) * HD + l];
        float v1 = g_met[(size_t)(b * TT + t) * HD + l + 32];
        float ss = v0 * v0 + v1 * v1;
#pragma unroll
        for (int off = 16; off; off >>= 1) ss += __shfl_xor_sync(0xffffffffu, ss, off);
        float nrm = sqrtf(ss);
        m_s[t * 65 + l]      = v0 / nrm;
        m_s[t * 65 + l + 32] = v1 / nrm;
    }
    __syncthreads();

    for (int i = w; i < TE; i += 8) {
        float bm = -INFINITY; int bi = 0;
        if (i != 0) {
            for (int j = l; j < TO; j += 32) {
                float s = 0.f;
#pragma unroll
                for (int d = 0; d < HD; d++) s += m_s[(2 * i) * 65 + d] * m_s[(2 * j + 1) * 65 + d];
                if (s > bm) { bm = s; bi = j; }
            }
        }
#pragma unroll
        for (int off = 16; off; off >>= 1) {
            float om = __shfl_xor_sync(0xffffffffu, bm, off);
            int   oi = __shfl_xor_sync(0xffffffffu, bi, off);
            if (om > bm || (om == bm && oi < bi)) { bm = om; bi = oi; }
        }
        if (l == 0) { node_max[i] = bm; node_idx[i] = bi; }
    }
    __syncthreads();

    if (tid < TE) {
        float v = node_max[tid];
        int c = 0;
        for (int j = 0; j < TE; j++) {
            float u = node_max[j];
            if (u > v || (u == v && j < tid)) c++;
        }
        rank_s[tid] = c;
    }
    __syncthreads();

    if (tid < TE) {
        int row;
        if (rank_s[tid] >= R_EFF) {
            int c = 0;
            for (int j = 0; j < tid; j++) if (rank_s[j] >= R_EFF) c++;
            row = c;
        } else {
            row = UNM + node_idx[tid];
        }
        rowmap_s[tid] = row;
        g_rowmap[b * TE + tid] = row;
    }
    for (int r = tid; r < TN; r += 256) sizes_s[r] = 0.f;
    __syncthreads();

    for (int t = tid; t < TT; t += 256) {
        int row = (t & 1) ? (UNM + (t >> 1)) : rowmap_s[t >> 1];
        atomicAdd(&sizes_s[row], attn_size[b * TT + t]);
        if (t >= 1) rci_out[(size_t)b * (TT - 1) + (t - 1)] = (float)(row - 1);
    }
    __syncthreads();
    for (int r = tid; r < TN; r += 256) g_nsz[b * TN + r] = sizes_s[r];
}

// ---------------- merge ----------------
__global__ void zero_x2() {
    int i = blockIdx.x * blockDim.x + threadIdx.x;
    if (i < BTN * DIMM) g_x2[i] = 0.f;
}

__global__ void merge_kernel(const float* __restrict__ attn_size) {
    int bt = blockIdx.x;
    int b = bt / TT, t = bt % TT;
    int row = (t & 1) ? (UNM + (t >> 1)) : g_rowmap[b * TE + (t >> 1)];
    float s = attn_size[bt];
    const float* src = g_x1 + (size_t)bt * DIMM;
    float* dst = g_x2 + ((size_t)b * TN + row) * DIMM;
    for (int d = threadIdx.x; d < DIMM; d += 256) atomicAdd(&dst[d], src[d] * s);
}

__global__ void finalize_kernel(float* __restrict__ out_ns) {
    int br = blockIdx.x;
    float ns = g_nsz[br];
    if (threadIdx.x == 0) out_ns[br] = ns;
    float* p = g_x2 + (size_t)br * DIMM;
    for (int d = threadIdx.x; d < DIMM; d += 256) p[d] = p[d] / ns;
}

// ---------------- launch ----------------
extern "C" void kernel_launch(void* const* d_in, const int* in_sizes, int n_in,
                              void* d_out, int out_size) {
    const float* x         = (const float*)d_in[0];
    const float* attn_size = (const float*)d_in[1];
    const float* ln1_g     = (const float*)d_in[2];
    const float* ln1_b     = (const float*)d_in[3];
    const float* w_qkv     = (const float*)d_in[4];
    const float* w_proj    = (const float*)d_in[5];
    const float* b_proj    = (const float*)d_in[6];
    const float* ln2_g     = (const float*)d_in[7];
    const float* ln2_b     = (const float*)d_in[8];
    const float* w_fc1     = (const float*)d_in[9];
    const float* b_fc1     = (const float*)d_in[10];
    const float* w_fc2     = (const float*)d_in[11];
    const float* b_fc2     = (const float*)d_in[12];

    float* out_x   = (float*)d_out;
    float* out_ns  = out_x + (size_t)BTN * DIMM;
    float* out_rci = out_ns + BTN;

    cudaFuncSetAttribute(attn_kernel, cudaFuncAttributeMaxDynamicSharedMemorySize, ATTN_SMEM);
    cudaFuncSetAttribute(match_kernel, cudaFuncAttributeMaxDynamicSharedMemorySize, MATCH_SMEM);
    cudaFuncSetAttribute(mma_gemm<false>, cudaFuncAttributeMaxDynamicSharedMemorySize, GSMEM_BYTES);
    cudaFuncSetAttribute(mma_gemm<true>,  cudaFuncAttributeMaxDynamicSharedMemorySize, GSMEM_BYTES);

    float *g_h_p, *g_o_p, *g_x2_p, *g_h2_p, *g_g_p, *g_qkv_p, *g_x1_p, *g_met_p, *g_wavg_p;
    cudaGetSymbolAddress((void**)&g_h_p,  g_h);
    cudaGetSymbolAddress((void**)&g_o_p,  g_o);
    cudaGetSymbolAddress((void**)&g_x2_p, g_x2);
    cudaGetSymbolAddress((void**)&g_h2_p, g_h2);
    cudaGetSymbolAddress((void**)&g_g_p,  g_g);
    cudaGetSymbolAddress((void**)&g_qkv_p, g_qkv);
    cudaGetSymbolAddress((void**)&g_x1_p, g_x1);
    cudaGetSymbolAddress((void**)&g_met_p, g_met);
    cudaGetSymbolAddress((void**)&g_wavg_p, g_wavg);

    // 1) LN1
    ln_kernel<<<BT, 256>>>(x, ln1_g, ln1_b, g_h_p);
    // 2) qkv (tf32 tensor cores)
    mma_gemm<false><<<dim3(3 * DIMM / 128, (BT + 127) / 128), 256, GSMEM_BYTES>>>(
        g_h_p, w_qkv, nullptr, nullptr, g_qkv_p, BT, 3 * DIMM, DIMM);
    // 3) attention
    attn_kernel<<<BB * HEADS, 256, ATTN_SMEM>>>(attn_size);
    // 4) x1 = x + o @ w_proj^T + b_proj (tf32)
    mma_gemm<false><<<dim3(DIMM / 128, (BT + 127) / 128), 256, GSMEM_BYTES>>>(
        g_o_p, w_proj, b_proj, x, g_x1_p, BT, DIMM, DIMM);
    // 5) metric = h @ W_avg^T (exact fp32 — correctness-critical matching path)
    wavg_kernel<<<(HD * DIMM + 255) / 256, 256>>>(w_qkv);
    gemm64_kernel<<<dim3(1, BT / 64), 256>>>(g_h_p, g_wavg_p, g_met_p, BT, HD, DIMM);
    // 6) matching
    match_kernel<<<BB, 256, MATCH_SMEM>>>(attn_size, out_rci);
    // 7-9) merge
    zero_x2<<<(BTN * DIMM + 255) / 256, 256>>>();
    merge_kernel<<<BT, 256>>>(attn_size);
    finalize_kernel<<<BTN, 256>>>(out_ns);
    // 10) LN2
    ln_kernel<<<BTN, 256>>>(g_x2_p, ln2_g, ln2_b, g_h2_p);
    // 11) MLP (tf32)
    mma_gemm<true><<<dim3(MLP_H / 128, (BTN + 127) / 128), 256, GSMEM_BYTES>>>(
        g_h2_p, w_fc1, b_fc1, nullptr, g_g_p, BTN, MLP_H, DIMM);
    mma_gemm<false><<<dim3(DIMM / 128, (BTN + 127) / 128), 256, GSMEM_BYTES>>>(
        g_g_p, w_fc2, b_fc2, g_x2_p, out_x, BTN, DIMM, MLP_H);
}

// round 8
// speedup vs baseline: 3.9531x; 1.1695x over previous
#include <cuda_runtime.h>
#include <math.h>
#include <stdint.h>

// ---------------- problem constants ----------------
#define BB     64
#define TT     197
#define DIMM   768
#define HEADS  12
#define HD     64
#define MLP_H  3072
#define R_EFF  16
#define TE     99
#define TO     98
#define UNM    (TE - R_EFF)  // 83
#define TN     (UNM + TO)    // 181
#define BT     (BB * TT)     // 12608
#define BTN    (BB * TN)     // 11584
#define LNEPS  1e-5f

// ---------------- scratch ----------------
__device__ float g_h   [BT  * DIMM];
__device__ float g_qkv [BT  * 3 * DIMM];
__device__ float g_o   [BT  * DIMM];
__device__ float g_x1  [BT  * DIMM];
__device__ float g_met [BT  * HD];
__device__ float g_wavg[HD * DIMM];
__device__ int   g_rowmap[BB * TE];
__device__ float g_nsz [BB * TN];
__device__ float g_x2  [BTN * DIMM];
__device__ float g_h2  [BTN * DIMM];
__device__ float g_g   [BTN * MLP_H];

// ---------------- layernorm ----------------
__global__ void ln_kernel(const float* __restrict__ x, const float* __restrict__ gam,
                          const float* __restrict__ bet, float* __restrict__ out) {
    int t = blockIdx.x;
    const float* p = x + (size_t)t * DIMM;
    int tid = threadIdx.x;
    float v[3]; float s = 0.f, ss = 0.f;
#pragma unroll
    for (int r = 0; r < 3; r++) { v[r] = p[tid + r * 256]; s += v[r]; ss += v[r] * v[r]; }
#pragma unroll
    for (int off = 16; off; off >>= 1) {
        s  += __shfl_xor_sync(0xffffffffu, s,  off);
        ss += __shfl_xor_sync(0xffffffffu, ss, off);
    }
    __shared__ float sm_s[8], sm_ss[8];
    if ((tid & 31) == 0) { sm_s[tid >> 5] = s; sm_ss[tid >> 5] = ss; }
    __syncthreads();
    if (tid < 32) {
        s  = (tid < 8) ? sm_s[tid]  : 0.f;
        ss = (tid < 8) ? sm_ss[tid] : 0.f;
#pragma unroll
        for (int off = 4; off; off >>= 1) {
            s  += __shfl_xor_sync(0xffffffffu, s,  off);
            ss += __shfl_xor_sync(0xffffffffu, ss, off);
        }
        if (tid == 0) { sm_s[0] = s; sm_ss[0] = ss; }
    }
    __syncthreads();
    float mean = sm_s[0] * (1.f / (float)DIMM);
    float var  = sm_ss[0] * (1.f / (float)DIMM) - mean * mean;
    float rs = rsqrtf(var + LNEPS);
    float* po = out + (size_t)t * DIMM;
#pragma unroll
    for (int r = 0; r < 3; r++) {
        int d = tid + r * 256;
        po[d] = (v[r] - mean) * rs * gam[d] + bet[d];
    }
}

// =====================================================================
// tf32 tensor-core GEMM, cp.async 3-stage pipeline, BK=32, 2 CTAs/SM,
// ldmatrix x4 fragment loads (A and B).
// C = A[M,K] * B[N,K]^T (+bias)(+res)(gelu)
// BM=128, BN=128, BK=32, 256 threads (8 warps 2x4, 64x32 warp tile).
// N % 128 == 0, K % 32 == 0 (KC >= 3), M arbitrary.
// stage: A [128][36] + B [128][36] words = 36 KB; 3 stages = 108 KB.
// Row stride 144 B => ldmatrix 8-row phases conflict-free (16m mod 128 distinct).
// =====================================================================
#define AROW  36                     // words per row (32 data + 4 pad)
#define ABYTES (128 * AROW * 4)      // 18432 B per matrix
#define SSTR  (2 * ABYTES)           // 36864 B per stage
#define NSTG  3
#define GSMEM_BYTES (NSTG * SSTR)    // 110592 B

__device__ __forceinline__ void cp16(uint32_t s, const void* g) {
    asm volatile("cp.async.cg.shared.global [%0], [%1], 16;\n" :: "r"(s), "l"(g));
}

template <bool GELU>
__global__ void __launch_bounds__(256, 2) mma_gemm(
    const float* __restrict__ A, const float* __restrict__ Bw,
    const float* __restrict__ bias, const float* __restrict__ res,
    float* __restrict__ C, int M, int N, int K)
{
    extern __shared__ float smf[];
    const uint32_t smb = (uint32_t)__cvta_generic_to_shared(smf);
    const int tid = threadIdx.x;
    const int lane = tid & 31, w = tid >> 5;
    const int wm = w >> 2, wn = w & 3;
    const int gid = lane >> 2, tig = lane & 3;
    const int bm = blockIdx.y * 128, bn = blockIdx.x * 128;
    const int KC = K >> 5;

    // staging: 4 A + 4 B 16B chunks per thread per stage
    size_t aOff[4]; uint32_t aw[4];
    size_t bOff[4]; uint32_t bw[4];
#pragma unroll
    for (int i = 0; i < 4; i++) {
        int idx = tid + 256 * i;          // 0..1023
        int row = idx >> 3, l16 = idx & 7;
        int gm = bm + row; if (gm > M - 1) gm = M - 1;
        aOff[i] = (size_t)gm * K + l16 * 4;
        aw[i]   = (uint32_t)(row * 144 + l16 * 16);
        bOff[i] = (size_t)(bn + row) * K + l16 * 4;
        bw[i]   = (uint32_t)(ABYTES + row * 144 + l16 * 16);
    }

    // ldmatrix per-lane byte offsets within tiles
    const uint32_t aLM = (uint32_t)((lane & 15) * 144 + (lane >> 4) * 16);
    const uint32_t bLM = (uint32_t)((((lane & 7) + ((lane >> 4) & 1) * 8)) * 144
                                    + ((lane >> 3) & 1) * 16);

    // prologue: stages 0..1
#pragma unroll
    for (int st = 0; st < NSTG - 1; st++) {
        uint32_t sb = smb + st * SSTR;
        size_t ko = (size_t)st * 32;
#pragma unroll
        for (int i = 0; i < 4; i++) {
            cp16(sb + aw[i], &A[aOff[i] + ko]);
            cp16(sb + bw[i], &Bw[bOff[i] + ko]);
        }
        asm volatile("cp.async.commit_group;\n" ::);
    }

    float acc[4][4][4];
#pragma unroll
    for (int mi = 0; mi < 4; mi++)
#pragma unroll
        for (int nj = 0; nj < 4; nj++)
#pragma unroll
            for (int c = 0; c < 4; c++) acc[mi][nj][c] = 0.f;

    for (int kt = 0; kt < KC; kt++) {
        asm volatile("cp.async.wait_group 1;\n" ::);
        __syncthreads();
        // prefetch stage kt+2 into slot (kt+2)%3 == (kt-1)%3 (consumed last iter)
        int kn = kt + NSTG - 1;
        if (kn < KC) {
            uint32_t sb = smb + (kn % NSTG) * SSTR;
            size_t ko = (size_t)kn * 32;
#pragma unroll
            for (int i = 0; i < 4; i++) {
                cp16(sb + aw[i], &A[aOff[i] + ko]);
                cp16(sb + bw[i], &Bw[bOff[i] + ko]);
            }
        }
        asm volatile("cp.async.commit_group;\n" ::);

        const uint32_t sbase = smb + (kt % NSTG) * SSTR;
        const uint32_t aBase = sbase + (uint32_t)(wm * 64) * 144 + aLM;
        const uint32_t bBase = sbase + ABYTES + (uint32_t)(wn * 32) * 144 + bLM;
#pragma unroll
        for (int s = 0; s < 4; s++) {
            uint32_t a[4][4];
#pragma unroll
            for (int mi = 0; mi < 4; mi++) {
                uint32_t ad = aBase + (uint32_t)(mi * 2304 + s * 32);
                asm volatile(
                    "ldmatrix.sync.aligned.m8n8.x4.shared.b16 {%0,%1,%2,%3}, [%4];"
                    : "=r"(a[mi][0]), "=r"(a[mi][1]), "=r"(a[mi][2]), "=r"(a[mi][3])
                    : "r"(ad));
            }
            uint32_t b[4][2];
#pragma unroll
            for (int nb = 0; nb < 2; nb++) {
                uint32_t bd = bBase + (uint32_t)(nb * 2304 + s * 32);
                asm volatile(
                    "ldmatrix.sync.aligned.m8n8.x4.shared.b16 {%0,%1,%2,%3}, [%4];"
                    : "=r"(b[2 * nb][0]), "=r"(b[2 * nb][1]),
                      "=r"(b[2 * nb + 1][0]), "=r"(b[2 * nb + 1][1])
                    : "r"(bd));
            }
#pragma unroll
            for (int mi = 0; mi < 4; mi++)
#pragma unroll
                for (int nj = 0; nj < 4; nj++) {
                    asm volatile(
                        "mma.sync.aligned.m16n8k8.row.col.f32.tf32.tf32.f32 "
                        "{%0,%1,%2,%3}, {%4,%5,%6,%7}, {%8,%9}, {%0,%1,%2,%3};"
                        : "+f"(acc[mi][nj][0]), "+f"(acc[mi][nj][1]),
                          "+f"(acc[mi][nj][2]), "+f"(acc[mi][nj][3])
                        : "r"(a[mi][0]), "r"(a[mi][1]), "r"(a[mi][2]), "r"(a[mi][3]),
                          "r"(b[nj][0]), "r"(b[nj][1]));
                }
        }
    }

    // ---- epilogue ----
    const int m_base = bm + wm * 64;
    const int n_base = bn + wn * 32;
#pragma unroll
    for (int mi = 0; mi < 4; mi++) {
        int r0 = m_base + mi * 16 + gid;
        int r1 = r0 + 8;
#pragma unroll
        for (int nj = 0; nj < 4; nj++) {
            int col = n_base + nj * 8 + 2 * tig;
            float2 v0 = make_float2(acc[mi][nj][0], acc[mi][nj][1]);
            float2 v1 = make_float2(acc[mi][nj][2], acc[mi][nj][3]);
            if (bias) {
                float2 bb = *(const float2*)&bias[col];
                v0.x += bb.x; v0.y += bb.y; v1.x += bb.x; v1.y += bb.y;
            }
            if (r0 < M) {
                if (res) {
                    float2 rr = *(const float2*)&res[(size_t)r0 * N + col];
                    v0.x += rr.x; v0.y += rr.y;
                }
                if (GELU) {
                    v0.x = 0.5f * v0.x * (1.f + erff(v0.x * 0.70710678118654752f));
                    v0.y = 0.5f * v0.y * (1.f + erff(v0.y * 0.70710678118654752f));
                }
                *(float2*)&C[(size_t)r0 * N + col] = v0;
            }
            if (r1 < M) {
                if (res) {
                    float2 rr = *(const float2*)&res[(size_t)r1 * N + col];
                    v1.x += rr.x; v1.y += rr.y;
                }
                if (GELU) {
                    v1.x = 0.5f * v1.x * (1.f + erff(v1.x * 0.70710678118654752f));
                    v1.y = 0.5f * v1.y * (1.f + erff(v1.y * 0.70710678118654752f));
                }
                *(float2*)&C[(size_t)r1 * N + col] = v1;
            }
        }
    }
}

// ---------------- exact fp32 GEMM (64x64 tile) for the metric path ----------------
__global__ void gemm64_kernel(const float* __restrict__ A, const float* __restrict__ Bw,
                              float* __restrict__ C, int M, int N, int K) {
    __shared__ float As[16][65];
    __shared__ float Bs[16][65];
    int tid = threadIdx.x;
    int tx = tid & 15, ty = tid >> 4;
    int bm = blockIdx.y * 64, bn = blockIdx.x * 64;
    const float* Ab = A  + (size_t)bm * K;
    const float* Bb = Bw + (size_t)bn * K;
    float acc[4][4] = {};
    for (int k0 = 0; k0 < K; k0 += 16) {
#pragma unroll
        for (int r = 0; r < 4; r++) {
            int row = ty + r * 16;
            As[tx][row] = Ab[(size_t)row * K + k0 + tx];
            Bs[tx][row] = Bb[(size_t)row * K + k0 + tx];
        }
        __syncthreads();
#pragma unroll
        for (int kk = 0; kk < 16; kk++) {
            float a[4], b[4];
#pragma unroll
            for (int i = 0; i < 4; i++) a[i] = As[kk][ty * 4 + i];
#pragma unroll
            for (int j = 0; j < 4; j++) b[j] = Bs[kk][tx * 4 + j];
#pragma unroll
            for (int i = 0; i < 4; i++)
#pragma unroll
                for (int j = 0; j < 4; j++) acc[i][j] += a[i] * b[j];
        }
        __syncthreads();
    }
#pragma unroll
    for (int i = 0; i < 4; i++) {
        int m = bm + ty * 4 + i;
#pragma unroll
        for (int j = 0; j < 4; j++) {
            int n = bn + tx * 4 + j;
            C[(size_t)m * N + n] = acc[i][j];
        }
    }
}

// ---------------- W_avg = mean over heads of w_k rows ----------------
__global__ void wavg_kernel(const float* __restrict__ w_qkv) {
    int i = blockIdx.x * blockDim.x + threadIdx.x;
    if (i >= HD * DIMM) return;
    int d = i / DIMM, c = i % DIMM;
    float s = 0.f;
#pragma unroll
    for (int h = 0; h < HEADS; h++)
        s += w_qkv[(size_t)(DIMM + h * HD + d) * DIMM + c];
    g_wavg[i] = s * (1.f / (float)HEADS);
}

// ---------------- attention: one block per (b,h), 8 warps ----------------
#define KVP 68
#define ATTN_SMEM ((TT * KVP * 2 + 8 * 64 + 8 * TT + TT) * 4)
__global__ void attn_kernel(const float* __restrict__ attn_size) {
    extern __shared__ float smf[];
    float* Ks = smf;
    float* Vs = Ks + TT * KVP;
    float* qs = Vs + TT * KVP;
    float* ps = qs + 8 * 64;
    float* Ls = ps + 8 * TT;
    int bh = blockIdx.x;
    int b = bh / HEADS, h = bh % HEADS;
    int tid = threadIdx.x, w = tid >> 5, l = tid & 31;

    for (int idx = tid; idx < TT * HD; idx += 256) {
        int j = idx >> 6, d = idx & 63;
        const float* base = g_qkv + (size_t)(b * TT + j) * (3 * DIMM) + h * HD + d;
        Ks[j * KVP + d] = base[DIMM];
        Vs[j * KVP + d] = base[2 * DIMM];
    }
    for (int j = tid; j < TT; j += 256) Ls[j] = logf(attn_size[b * TT + j]);
    __syncthreads();

    const float scale = 0.125f;
    for (int i = w; i < TT; i += 8) {
        const float* qp = g_qkv + (size_t)(b * TT + i) * (3 * DIMM) + h * HD;
        qs[w * 64 + l]      = qp[l];
        qs[w * 64 + l + 32] = qp[l + 32];
        __syncwarp();
        const float4* q4 = (const float4*)&qs[w * 64];
        float sreg[7];
        float mx = -INFINITY;
        int cnt = 0;
        for (int j = l; j < TT; j += 32, cnt++) {
            const float4* k4 = (const float4*)&Ks[j * KVP];
            float s = 0.f;
#pragma unroll
            for (int d4 = 0; d4 < 16; d4++) {
                float4 kv = k4[d4], qv = q4[d4];
                s += qv.x * kv.x + qv.y * kv.y + qv.z * kv.z + qv.w * kv.w;
            }
            s = s * scale + Ls[j];
            sreg[cnt] = s;
            mx = fmaxf(mx, s);
        }
#pragma unroll
        for (int off = 16; off; off >>= 1) mx = fmaxf(mx, __shfl_xor_sync(0xffffffffu, mx, off));
        float sum = 0.f;
        cnt = 0;
        for (int j = l; j < TT; j += 32, cnt++) {
            float e = expf(sreg[cnt] - mx);
            sreg[cnt] = e;
            sum += e;
        }
#pragma unroll
        for (int off = 16; off; off >>= 1) sum += __shfl_xor_sync(0xffffffffu, sum, off);
        float inv = 1.f / sum;
        cnt = 0;
        for (int j = l; j < TT; j += 32, cnt++) ps[w * TT + j] = sreg[cnt] * inv;
        __syncwarp();
#pragma unroll
        for (int dd = 0; dd < 2; dd++) {
            int d = l + dd * 32;
            float acc = 0.f;
            int j = 0;
            for (; j + 4 <= TT; j += 4) {
                acc += ps[w * TT + j + 0] * Vs[(j + 0) * KVP + d];
                acc += ps[w * TT + j + 1] * Vs[(j + 1) * KVP + d];
                acc += ps[w * TT + j + 2] * Vs[(j + 2) * KVP + d];
                acc += ps[w * TT + j + 3] * Vs[(j + 3) * KVP + d];
            }
            for (; j < TT; j++) acc += ps[w * TT + j] * Vs[j * KVP + d];
            g_o[(size_t)(b * TT + i) * DIMM + h * HD + d] = acc;
        }
        __syncwarp();
    }
}

// ---------------- matching: one block per batch ----------------
#define MATCH_SMEM (TT * 65 * 4)
__global__ void match_kernel(const float* __restrict__ attn_size, float* __restrict__ rci_out) {
    extern __shared__ float m_s[];
    __shared__ float node_max[TE];
    __shared__ int   node_idx[TE];
    __shared__ int   rank_s[TE];
    __shared__ int   rowmap_s[TE];
    __shared__ float sizes_s[TN];
    int b = blockIdx.x;
    int tid = threadIdx.x, w = tid >> 5, l = tid & 31;

    for (int t = w; t < TT; t += 8) {
        float v0 = g_met[(size_t)(b * TT + t) * HD + l];
        float v1 = g_met[(size_t)(b * TT + t) * HD + l + 32];
        float ss = v0 * v0 + v1 * v1;
#pragma unroll
        for (int off = 16; off; off >>= 1) ss += __shfl_xor_sync(0xffffffffu, ss, off);
        float nrm = sqrtf(ss);
        m_s[t * 65 + l]      = v0 / nrm;
        m_s[t * 65 + l + 32] = v1 / nrm;
    }
    __syncthreads();

    for (int i = w; i < TE; i += 8) {
        float bm = -INFINITY; int bi = 0;
        if (i != 0) {
            for (int j = l; j < TO; j += 32) {
                float s = 0.f;
#pragma unroll
                for (int d = 0; d < HD; d++) s += m_s[(2 * i) * 65 + d] * m_s[(2 * j + 1) * 65 + d];
                if (s > bm) { bm = s; bi = j; }
            }
        }
#pragma unroll
        for (int off = 16; off; off >>= 1) {
            float om = __shfl_xor_sync(0xffffffffu, bm, off);
            int   oi = __shfl_xor_sync(0xffffffffu, bi, off);
            if (om > bm || (om == bm && oi < bi)) { bm = om; bi = oi; }
        }
        if (l == 0) { node_max[i] = bm; node_idx[i] = bi; }
    }
    __syncthreads();

    if (tid < TE) {
        float v = node_max[tid];
        int c = 0;
        for (int j = 0; j < TE; j++) {
            float u = node_max[j];
            if (u > v || (u == v && j < tid)) c++;
        }
        rank_s[tid] = c;
    }
    __syncthreads();

    if (tid < TE) {
        int row;
        if (rank_s[tid] >= R_EFF) {
            int c = 0;
            for (int j = 0; j < tid; j++) if (rank_s[j] >= R_EFF) c++;
            row = c;
        } else {
            row = UNM + node_idx[tid];
        }
        rowmap_s[tid] = row;
        g_rowmap[b * TE + tid] = row;
    }
    for (int r = tid; r < TN; r += 256) sizes_s[r] = 0.f;
    __syncthreads();

    for (int t = tid; t < TT; t += 256) {
        int row = (t & 1) ? (UNM + (t >> 1)) : rowmap_s[t >> 1];
        atomicAdd(&sizes_s[row], attn_size[b * TT + t]);
        if (t >= 1) rci_out[(size_t)b * (TT - 1) + (t - 1)] = (float)(row - 1);
    }
    __syncthreads();
    for (int r = tid; r < TN; r += 256) g_nsz[b * TN + r] = sizes_s[r];
}

// ---------------- merge: write phase (each output row exactly once) ----------------
__global__ void merge_write(const float* __restrict__ attn_size) {
    int bt = blockIdx.x;
    int b = bt / TT, t = bt % TT;
    int row;
    if (t & 1) {
        row = UNM + (t >> 1);
    } else {
        row = g_rowmap[b * TE + (t >> 1)];
        if (row >= UNM) return;   // merged even: handled by merge_add
    }
    float s = attn_size[bt];
    const float4* src = (const float4*)(g_x1 + (size_t)bt * DIMM);
    float4* dst = (float4*)(g_x2 + ((size_t)b * TN + row) * DIMM);
    int d = threadIdx.x;         // 192 threads, 192 float4 = 768 floats
    float4 v = src[d];
    v.x *= s; v.y *= s; v.z *= s; v.w *= s;
    dst[d] = v;
}

// ---------------- merge: add phase (only merged evens, ~16 per batch) ----------------
__global__ void merge_add(const float* __restrict__ attn_size) {
    int b = blockIdx.x / TE, i = blockIdx.x % TE;
    int row = g_rowmap[b * TE + i];
    if (row < UNM) return;
    int bt = b * TT + 2 * i;
    float s = attn_size[bt];
    const float* src = g_x1 + (size_t)bt * DIMM;
    float* dst = g_x2 + ((size_t)b * TN + row) * DIMM;
    for (int d = threadIdx.x; d < DIMM; d += 256)
        atomicAdd(&dst[d], src[d] * s);
}

__global__ void finalize_kernel(float* __restrict__ out_ns) {
    int br = blockIdx.x;
    float ns = g_nsz[br];
    if (threadIdx.x == 0) out_ns[br] = ns;
    float inv = 1.f / ns;
    float4* p = (float4*)(g_x2 + (size_t)br * DIMM);
    int d = threadIdx.x;         // 192 threads
    float4 v = p[d];
    v.x *= inv; v.y *= inv; v.z *= inv; v.w *= inv;
    p[d] = v;
}

// ---------------- launch ----------------
extern "C" void kernel_launch(void* const* d_in, const int* in_sizes, int n_in,
                              void* d_out, int out_size) {
    const float* x         = (const float*)d_in[0];
    const float* attn_size = (const float*)d_in[1];
    const float* ln1_g     = (const float*)d_in[2];
    const float* ln1_b     = (const float*)d_in[3];
    const float* w_qkv     = (const float*)d_in[4];
    const float* w_proj    = (const float*)d_in[5];
    const float* b_proj    = (const float*)d_in[6];
    const float* ln2_g     = (const float*)d_in[7];
    const float* ln2_b     = (const float*)d_in[8];
    const float* w_fc1     = (const float*)d_in[9];
    const float* b_fc1     = (const float*)d_in[10];
    const float* w_fc2     = (const float*)d_in[11];
    const float* b_fc2     = (const float*)d_in[12];

    float* out_x   = (float*)d_out;
    float* out_ns  = out_x + (size_t)BTN * DIMM;
    float* out_rci = out_ns + BTN;

    // one-time host objects (created during the correctness call, before capture)
    static cudaStream_t s2 = nullptr;
    static cudaEvent_t evF = nullptr, evJ = nullptr;
    if (!s2) {
        cudaStreamCreateWithFlags(&s2, cudaStreamNonBlocking);
        cudaEventCreateWithFlags(&evF, cudaEventDisableTiming);
        cudaEventCreateWithFlags(&evJ, cudaEventDisableTiming);
    }

    cudaFuncSetAttribute(attn_kernel, cudaFuncAttributeMaxDynamicSharedMemorySize, ATTN_SMEM);
    cudaFuncSetAttribute(match_kernel, cudaFuncAttributeMaxDynamicSharedMemorySize, MATCH_SMEM);
    cudaFuncSetAttribute(mma_gemm<false>, cudaFuncAttributeMaxDynamicSharedMemorySize, GSMEM_BYTES);
    cudaFuncSetAttribute(mma_gemm<true>,  cudaFuncAttributeMaxDynamicSharedMemorySize, GSMEM_BYTES);

    float *g_h_p, *g_o_p, *g_x2_p, *g_h2_p, *g_g_p, *g_qkv_p, *g_x1_p, *g_met_p, *g_wavg_p;
    cudaGetSymbolAddress((void**)&g_h_p,  g_h);
    cudaGetSymbolAddress((void**)&g_o_p,  g_o);
    cudaGetSymbolAddress((void**)&g_x2_p, g_x2);
    cudaGetSymbolAddress((void**)&g_h2_p, g_h2);
    cudaGetSymbolAddress((void**)&g_g_p,  g_g);
    cudaGetSymbolAddress((void**)&g_qkv_p, g_qkv);
    cudaGetSymbolAddress((void**)&g_x1_p, g_x1);
    cudaGetSymbolAddress((void**)&g_met_p, g_met);
    cudaGetSymbolAddress((void**)&g_wavg_p, g_wavg);

    // 1) LN1 (stream 0)
    ln_kernel<<<BT, 256>>>(x, ln1_g, ln1_b, g_h_p);

    // fork: matching branch on s2 (depends only on g_h, w_qkv, attn_size)
    cudaEventRecord(evF, 0);
    cudaStreamWaitEvent(s2, evF, 0);
    wavg_kernel<<<(HD * DIMM + 255) / 256, 256, 0, s2>>>(w_qkv);
    gemm64_kernel<<<dim3(1, BT / 64), 256, 0, s2>>>(g_h_p, g_wavg_p, g_met_p, BT, HD, DIMM);
    match_kernel<<<BB, 256, MATCH_SMEM, s2>>>(attn_size, out_rci);
    cudaEventRecord(evJ, s2);

    // main branch (stream 0): qkv -> attention -> proj
    mma_gemm<false><<<dim3(3 * DIMM / 128, (BT + 127) / 128), 256, GSMEM_BYTES>>>(
        g_h_p, w_qkv, nullptr, nullptr, g_qkv_p, BT, 3 * DIMM, DIMM);
    attn_kernel<<<BB * HEADS, 256, ATTN_SMEM>>>(attn_size);
    mma_gemm<false><<<dim3(DIMM / 128, (BT + 127) / 128), 256, GSMEM_BYTES>>>(
        g_o_p, w_proj, b_proj, x, g_x1_p, BT, DIMM, DIMM);

    // join
    cudaStreamWaitEvent(0, evJ, 0);

    // merge (write + sparse add), finalize
    merge_write<<<BT, 192>>>(attn_size);
    merge_add<<<BB * TE, 256>>>(attn_size);
    finalize_kernel<<<BTN, 192>>>(out_ns);
    // LN2
    ln_kernel<<<BTN, 256>>>(g_x2_p, ln2_g, ln2_b, g_h2_p);
    // MLP
    mma_gemm<true><<<dim3(MLP_H / 128, (BTN + 127) / 128), 256, GSMEM_BYTES>>>(
        g_h2_p, w_fc1, b_fc1, nullptr, g_g_p, BTN, MLP_H, DIMM);
    mma_gemm<false><<<dim3(DIMM / 128, (BTN + 127) / 128), 256, GSMEM_BYTES>>>(
        g_g_p, w_fc2, b_fc2, g_x2_p, out_x, BTN, DIMM, MLP_H);
}